// round 2
// baseline (speedup 1.0000x reference)
#include <cuda_runtime.h>

// GTConvAE, fully-fused persistent kernel with software grid barriers.
//
// Math identity (Kronecker mixed-product): with S = sum_{a,b<2} s[a][b] kron(St^a, Sg^b)
// and St the cyclic delay, S^k x[tau] = sum_{a,b<3} c_k[a][b] * Sg^b x[(tau-a) mod t],
// c_0 = delta, c_1 = s, c_2 = s conv s. So each conv layer = two shared GEMMs
// (G1 = Sg@act, G2 = Sg2@act) + a 9-term combine with folded filters
// H[o][i][a][b] = sum_k h[o][i][k] c_k[a][b]. Encoder fuses maxpool+relu; decoder
// exploits zero-stuffed upsampling (odd timesteps are zero -> skipped).
//
// Persistent layout: 96 blocks. Block bid: mat = bid/48 (0:Sg, 1:Sg2),
// mb = bid%6 (32-row m-band), jb = (bid%48)/6 (32-col j-tile). Each block keeps
// its A band (32x192) in smem across all layer GEMMs.

#define NN  192
#define TT  32
#define NB  96
#define ASP 196   // A smem row stride (floats), mult of 4 for float4
#define BSP 100   // B smem row stride (floats), mult of 4

// ---------------- scratch (device globals; no allocation allowed) -------------
__device__ float g_Sg2 [NN * NN];
__device__ float g_G1  [256 * NN];
__device__ float g_G2  [256 * NN];
__device__ float g_actA[256 * NN];
__device__ float g_actB[256 * NN];
__device__ unsigned g_cnt = 0;
__device__ volatile unsigned g_gen = 0;

// ---------------- grid barrier (generation-based, graph-replay safe) ----------
__device__ __forceinline__ void grid_barrier()
{
    __syncthreads();
    if (threadIdx.x == 0) {
        __threadfence();
        unsigned gen = g_gen;                 // read BEFORE arriving: safe, barrier
        if (atomicAdd(&g_cnt, 1u) == NB - 1) {//   can't complete without our arrive
            g_cnt = 0;
            __threadfence();
            g_gen = gen + 1;
        } else {
            while (g_gen == gen) __nanosleep(32);
        }
        __threadfence();
    }
    __syncthreads();
}

// ---------------- smem loaders -------------------------------------------------
// A band: As[ml*ASP + k] = A[(m0+ml)*192 + k]  (coalesced reads, scalar stores)
__device__ __forceinline__ void load_band(float* As, const float* __restrict__ A,
                                          int m0, int tid, bool l2only)
{
    for (int idx = tid; idx < 32 * NN; idx += 256) {
        int ml = idx / NN, q = idx % NN;
        const float* p = &A[(m0 + ml) * NN + q];
        As[ml * ASP + q] = l2only ? __ldcg(p) : *p;
    }
}

// ---------------- 32x32 output tile GEMM, A resident in smem -------------------
// C[m, j] = sum_k A[m,k] * B[k,j], k = 192, in two 96-deep chunks of B.
// BSRC: 0 = activation [j*192 + k] (ldcg), 1 = Sg column-slice, 2 = X ([k*32+j]).
template <int BSRC>
__device__ __noinline__ void gemm_tile(const float* __restrict__ As, float* __restrict__ Bs,
                                       const float* __restrict__ Bg, int j0,
                                       float* __restrict__ C, int osM, int osJ,
                                       int m0, int tid, int tx, int ty)
{
    float acc00 = 0.f, acc01 = 0.f, acc10 = 0.f, acc11 = 0.f;
    #pragma unroll
    for (int c = 0; c < 2; c++) {
        // --- load B chunk into Bs[j][k] (32 x 96, stride BSP) ---
        if (BSRC == 0) {
            for (int idx = tid; idx < 32 * 96; idx += 256) {
                int jl = idx / 96, q = idx % 96;
                Bs[jl * BSP + q] = __ldcg(&Bg[(j0 + jl) * NN + 96 * c + q]);
            }
        } else if (BSRC == 1) {
            for (int idx = tid; idx < 32 * 96; idx += 256) {
                int kk = idx >> 5, jl = idx & 31;
                Bs[jl * BSP + kk] = Bg[(96 * c + kk) * NN + j0 + jl];
            }
        } else {
            for (int idx = tid; idx < 32 * 96; idx += 256) {
                int kk = idx >> 5, jl = idx & 31;
                Bs[jl * BSP + kk] = Bg[(96 * c + kk) * TT + jl];
            }
        }
        __syncthreads();

        const float* ap0 = As + (2 * ty) * ASP + 96 * c;
        const float* ap1 = ap0 + ASP;
        const float* bp0 = Bs + (2 * tx) * BSP;
        const float* bp1 = bp0 + BSP;
        #pragma unroll
        for (int k = 0; k < 96; k += 4) {
            float4 a0 = *(const float4*)(ap0 + k);
            float4 a1 = *(const float4*)(ap1 + k);
            float4 b0 = *(const float4*)(bp0 + k);
            float4 b1 = *(const float4*)(bp1 + k);
            acc00 += a0.x * b0.x; acc00 += a0.y * b0.y; acc00 += a0.z * b0.z; acc00 += a0.w * b0.w;
            acc01 += a0.x * b1.x; acc01 += a0.y * b1.y; acc01 += a0.z * b1.z; acc01 += a0.w * b1.w;
            acc10 += a1.x * b0.x; acc10 += a1.y * b0.y; acc10 += a1.z * b0.z; acc10 += a1.w * b0.w;
            acc11 += a1.x * b1.x; acc11 += a1.y * b1.y; acc11 += a1.z * b1.z; acc11 += a1.w * b1.w;
        }
        __syncthreads();
    }
    const int m = m0 + 2 * ty, j = j0 + 2 * tx;
    C[(m    ) * osM + (j    ) * osJ] = acc00;
    C[(m    ) * osM + (j + 1) * osJ] = acc01;
    C[(m + 1) * osM + (j    ) * osJ] = acc10;
    C[(m + 1) * osM + (j + 1) * osJ] = acc11;
}

// ---------------- folded filters ----------------------------------------------
__device__ __forceinline__ float fold_H(const float* __restrict__ h3,
                                        const float sv[4], int a, int b)
{
    float c0 = (a == 0 && b == 0) ? 1.f : 0.f;
    float c1 = (a < 2 && b < 2) ? sv[a * 2 + b] : 0.f;
    float c2 = 0.f;
    #pragma unroll
    for (int a1 = 0; a1 < 2; a1++)
        #pragma unroll
        for (int b1 = 0; b1 < 2; b1++) {
            int a2 = a - a1, b2 = b - b1;
            if (a2 >= 0 && a2 < 2 && b2 >= 0 && b2 < 2)
                c2 += sv[a1 * 2 + b1] * sv[a2 * 2 + b2];
        }
    return h3[0] * c0 + h3[1] * c1 + h3[2] * c2;
}

// ---------------- encoder combine: conv-combine + maxpool(R=2) + relu ---------
template <int CI, int CO, int OT>
__device__ __noinline__ void combine_enc_dev(
    const float* __restrict__ G0, int g0sT, int g0sI, int g0sN,
    const float* __restrict__ G1, const float* __restrict__ G2,
    const float* __restrict__ h, const float* __restrict__ s,
    float* __restrict__ out, int t, int tp, int obg, float* Hs, int tid)
{
    const int ob = obg * OT;
    const float sv[4] = { s[0], s[1], s[2], s[3] };
    for (int idx = tid; idx < CI * 9 * OT; idx += 256) {
        int oo = idx % OT;
        int tmp = idx / OT;
        int b = tmp % 3, a = (tmp / 3) % 3, i = tmp / 9;
        Hs[idx] = fold_H(&h[((ob + oo) * CI + i) * 3], sv, a, b);
    }
    __syncthreads();
    if (tid < NN) {
        const int n = tid;
        float acc0[OT], acc1[OT];
        #pragma unroll
        for (int o = 0; o < OT; o++) { acc0[o] = 0.f; acc1[o] = 0.f; }
        const int t0 = 2 * tp, t1 = 2 * tp + 1;
        #pragma unroll
        for (int a = 0; a < 3; a++) {
            int s0 = t0 - a; if (s0 < 0) s0 += t;
            int s1 = t1 - a; if (s1 < 0) s1 += t;
            #pragma unroll
            for (int i = 0; i < CI; i++) {
                float v00 = __ldcg(&G0[s0 * g0sT + i * g0sI + n * g0sN]);
                float v01 = __ldcg(&G0[s1 * g0sT + i * g0sI + n * g0sN]);
                float v10 = __ldcg(&G1[(s0 * CI + i) * NN + n]);
                float v11 = __ldcg(&G1[(s1 * CI + i) * NN + n]);
                float v20 = __ldcg(&G2[(s0 * CI + i) * NN + n]);
                float v21 = __ldcg(&G2[(s1 * CI + i) * NN + n]);
                const float* Hp = &Hs[(i * 3 + a) * 3 * OT];
                #pragma unroll
                for (int o = 0; o < OT; o++) {
                    acc0[o] += Hp[o] * v00 + Hp[OT + o] * v10 + Hp[2 * OT + o] * v20;
                    acc1[o] += Hp[o] * v01 + Hp[OT + o] * v11 + Hp[2 * OT + o] * v21;
                }
            }
        }
        #pragma unroll
        for (int o = 0; o < OT; o++)
            out[(tp * CO + (ob + o)) * NN + n] = fmaxf(fmaxf(acc0[o], acc1[o]), 0.f);
    }
}

// ---------------- decoder combine (zero-stuffed upsampled input) ---------------
template <int CI, int CO, int OT, bool RELU, bool FINAL>
__device__ __noinline__ void combine_dec_dev(
    const float* __restrict__ G0, const float* __restrict__ G1,
    const float* __restrict__ G2,
    const float* __restrict__ h, const float* __restrict__ s,
    float* __restrict__ out, int t, int tau, int obg, float* Hs, int tid)
{
    const int ob = obg * OT;
    const float sv[4] = { s[0], s[1], s[2], s[3] };
    for (int idx = tid; idx < CI * 9 * OT; idx += 256) {
        int oo = idx % OT;
        int tmp = idx / OT;
        int b = tmp % 3, a = (tmp / 3) % 3, i = tmp / 9;
        Hs[idx] = fold_H(&h[((ob + oo) * CI + i) * 3], sv, a, b);
    }
    __syncthreads();
    if (tid < NN) {
        const int n = tid;
        float acc[OT];
        #pragma unroll
        for (int o = 0; o < OT; o++) acc[o] = 0.f;
        #pragma unroll
        for (int a = 0; a < 3; a++) {
            int src = tau - a; if (src < 0) src += t;
            if (src & 1) continue;              // zero-stuffed upsample
            int tl = src >> 1;
            #pragma unroll
            for (int i = 0; i < CI; i++) {
                float v0 = __ldcg(&G0[(tl * CI + i) * NN + n]);
                float v1 = __ldcg(&G1[(tl * CI + i) * NN + n]);
                float v2 = __ldcg(&G2[(tl * CI + i) * NN + n]);
                const float* Hp = &Hs[(i * 3 + a) * 3 * OT];
                #pragma unroll
                for (int o = 0; o < OT; o++)
                    acc[o] += Hp[o] * v0 + Hp[OT + o] * v1 + Hp[2 * OT + o] * v2;
            }
        }
        if (FINAL) {
            out[n * t + tau] = acc[0];          // inversevec -> (N, T)
        } else {
            #pragma unroll
            for (int o = 0; o < OT; o++) {
                float v = acc[o];
                if (RELU) v = fmaxf(v, 0.f);
                out[(tau * CO + (ob + o)) * NN + n] = v;
            }
        }
    }
}

// ---------------- the fused persistent kernel ----------------------------------
__global__ __launch_bounds__(256, 1) void mega(
    const float* __restrict__ X,   const float* __restrict__ Sg,
    const float* __restrict__ s,   const float* __restrict__ h_e1,
    const float* __restrict__ h_e2, const float* __restrict__ h_d1,
    const float* __restrict__ h_d2, float* __restrict__ out)
{
    __shared__ float As[32 * ASP];   // persistent A band (Sg or Sg2 rows)
    __shared__ float Bs[32 * BSP];   // per-stage B chunk
    __shared__ float Hs[1152];       // combine filter table (max: CI=32, OT=4)

    const int tid = threadIdx.x;
    const int tx = tid & 15, ty = tid >> 4;
    const int bid = blockIdx.x;
    const int mat = bid / 48;            // 0: Sg band, 1: Sg2 band
    const int mb  = bid % 6;
    const int jb  = (bid % 48) / 6;      // 0..7
    const int m0  = mb * 32, j0 = jb * 32;

    // ---- S0: Sg2 tiles (blocks 0-35) + G1_e1 = Sg @ X (blocks 36-41);
    //          all mat==0 blocks load their persistent Sg band.
    if (mat == 0) {
        load_band(As, Sg, m0, tid, false);
        if (bid < 36) {
            gemm_tile<1>(As, Bs, Sg, (bid / 6) * 32, g_Sg2, NN, 1, m0, tid, tx, ty);
        } else if (bid < 42) {
            gemm_tile<2>(As, Bs, X, 0, g_G1, 1, NN, m0, tid, tx, ty);
        }
    }
    grid_barrier();

    // ---- S1: mat==1 blocks load Sg2 bands; blocks 48-53 compute G2_e1 = Sg2 @ X.
    if (mat == 1) {
        load_band(As, g_Sg2, m0, tid, true);
        if (bid < 54)
            gemm_tile<2>(As, Bs, X, 0, g_G2, 1, NN, m0, tid, tx, ty);
    }
    grid_barrier();

    // ---- S2: combine e1 -> actA [16t][16c][192n] ----
    if (bid < 16)
        combine_enc_dev<1, 16, 16>(X, 1, 0, TT, g_G1, g_G2, h_e1, s,
                                   g_actA, TT, bid, 0, Hs, tid);
    grid_barrier();

    // ---- S3: e2 GEMMs (all 96 blocks), B = actA ----
    gemm_tile<0>(As, Bs, g_actA, j0, mat ? g_G2 : g_G1, 1, NN, m0, tid, tx, ty);
    grid_barrier();

    // ---- S4: combine e2 -> actB [8t][32c][192n] ----
    if (bid < 64)
        combine_enc_dev<16, 32, 4>(g_actA, 16 * NN, NN, 1, g_G1, g_G2, h_e2, s,
                                   g_actB, 16, bid & 7, bid >> 3, Hs, tid);
    grid_barrier();

    // ---- S5: d1 GEMMs, B = actB ----
    gemm_tile<0>(As, Bs, g_actB, j0, mat ? g_G2 : g_G1, 1, NN, m0, tid, tx, ty);
    grid_barrier();

    // ---- S6: combine d1 -> actA [16t][16c][192n] ----
    if (bid < 64)
        combine_dec_dev<32, 16, 4, true, false>(g_actB, g_G1, g_G2, h_d1, s,
                                                g_actA, 16, bid & 15, bid >> 4, Hs, tid);
    grid_barrier();

    // ---- S7: d2 GEMMs, B = actA ----
    gemm_tile<0>(As, Bs, g_actA, j0, mat ? g_G2 : g_G1, 1, NN, m0, tid, tx, ty);
    grid_barrier();

    // ---- S8: combine d2 -> out (N, T) ----
    if (bid < 32)
        combine_dec_dev<16, 1, 1, false, true>(g_actA, g_G1, g_G2, h_d2, s,
                                               out, TT, bid, 0, Hs, tid);
}

// ---------------- launch --------------------------------------------------------
extern "C" void kernel_launch(void* const* d_in, const int* in_sizes, int n_in,
                              void* d_out, int out_size)
{
    const float* X    = (const float*)d_in[0];  // (192, 32)
    const float* Sg   = (const float*)d_in[1];  // (192, 192)
    const float* s    = (const float*)d_in[2];  // (2, 2)
    const float* h_e1 = (const float*)d_in[3];  // (16, 1, 3)
    const float* h_e2 = (const float*)d_in[4];  // (32, 16, 3)
    const float* h_d1 = (const float*)d_in[5];  // (16, 32, 3)
    const float* h_d2 = (const float*)d_in[6];  // (1, 16, 3)
    float* out = (float*)d_out;

    mega<<<NB, 256>>>(X, Sg, s, h_e1, h_e2, h_d1, h_d2, out);
}

// round 3
// speedup vs baseline: 1.1314x; 1.1314x over previous
#include <cuda_runtime.h>

// GTConvAE — fully-fused persistent kernel, R3.
// Kronecker identity: S^k x[tau] = sum_{a,b<3} c_k[a][b] * Sg^b x[(tau-a) mod t],
// c_0=delta, c_1=s, c_2=s*s (2D conv). Layer = two GEMMs (Sg@act, Sg2@act) +
// 9-term combine with folded filters H[o][i][a][b] = sum_k h[o][i][k] c_k[a][b].
// Encoder fuses maxpool(R=2)+relu; decoder exploits zero-stuffed upsampling.

#define NN  192
#define TT  32
#define NB  96
#define ASP 34    // smem k-row stride for A [k][m]
#define BSP 34    // smem k-row stride for B [k][j]

// ---------------- scratch --------------------------------------------------------
__device__ float g_Sg2 [NN * NN];
__device__ float g_G1  [256 * NN];   // also holds P = Sg@X for layer e1
__device__ float g_G2  [256 * NN];
__device__ float g_actA[256 * NN];
__device__ float g_actB[256 * NN];
__device__ unsigned g_cnt = 0;
__device__ volatile unsigned g_gen = 0;

// ---------------- grid barrier ---------------------------------------------------
__device__ __forceinline__ void grid_barrier()
{
    __syncthreads();
    if (threadIdx.x == 0) {
        __threadfence();
        unsigned gen = g_gen;                  // read BEFORE arrive
        if (atomicAdd(&g_cnt, 1u) == NB - 1) {
            g_cnt = 0;
            __threadfence();
            g_gen = gen + 1;
        } else {
            while (g_gen == gen) { }
        }
        __threadfence();
    }
    __syncthreads();
}

// ---------------- GEMM stage: C = A(192x192) @ B(192xJ), one 32x32 tile ----------
// smem k-major: As[k][m], Bs[k][j] -> A reads broadcast, B reads 128B/warp.
// bmode: 0 = act layout [j*192+k] (ldcg), 1 = Sg cols [k*192+j0+j], 2 = X [k*32+j]
__device__ void gemm_stage(const float* __restrict__ A, bool a_cg,
                           const float* __restrict__ Bg, int bmode, int j0,
                           float* __restrict__ C, bool c_row, int m0,
                           float* As, float* Bs)
{
    const int tid = threadIdx.x;
    const int tx = tid & 15, ty = tid >> 4;

    // A band 32m x 192k -> As[k][m]  (coalesced along k; 2-way smem write conflict)
    #pragma unroll
    for (int r = 0; r < 24; r++) {
        int idx = tid + 256 * r;
        int ml = idx / NN, q = idx - ml * NN;
        const float* p = &A[(m0 + ml) * NN + q];
        As[q * ASP + ml] = a_cg ? __ldcg(p) : *p;
    }

    float acc00 = 0.f, acc01 = 0.f, acc10 = 0.f, acc11 = 0.f;
    #pragma unroll
    for (int c = 0; c < 2; c++) {
        // B chunk: 96k x 32j -> Bs[k][j]
        if (bmode == 0) {
            #pragma unroll
            for (int r = 0; r < 12; r++) {
                int idx = tid + 256 * r;
                int jl = idx / 96, q = idx - jl * 96;
                Bs[q * BSP + jl] = __ldcg(&Bg[(j0 + jl) * NN + 96 * c + q]);
            }
        } else if (bmode == 1) {
            #pragma unroll
            for (int r = 0; r < 12; r++) {
                int idx = tid + 256 * r;
                int kk = idx >> 5, jl = idx & 31;
                Bs[kk * BSP + jl] = Bg[(96 * c + kk) * NN + j0 + jl];
            }
        } else {
            #pragma unroll
            for (int r = 0; r < 12; r++) {
                int idx = tid + 256 * r;
                int kk = idx >> 5, jl = idx & 31;
                Bs[kk * BSP + jl] = Bg[(96 * c + kk) * TT + jl];
            }
        }
        __syncthreads();
        const float* ap = As + 96 * c * ASP + 2 * ty;
        const float* bp = Bs + 2 * tx;
        #pragma unroll 8
        for (int kk = 0; kk < 96; kk++) {
            float2 a = *(const float2*)(ap + kk * ASP);
            float2 b = *(const float2*)(bp + kk * BSP);
            acc00 += a.x * b.x; acc01 += a.x * b.y;
            acc10 += a.y * b.x; acc11 += a.y * b.y;
        }
        __syncthreads();
    }
    const int m = m0 + 2 * ty, j = j0 + 2 * tx;
    if (c_row) {
        C[(m    ) * NN + j] = acc00; C[(m    ) * NN + j + 1] = acc01;
        C[(m + 1) * NN + j] = acc10; C[(m + 1) * NN + j + 1] = acc11;
    } else {                             // [j*192 + m]
        C[(j    ) * NN + m] = acc00; C[(j + 1) * NN + m] = acc01;
        C[(j    ) * NN + m + 1] = acc10; C[(j + 1) * NN + m + 1] = acc11;
    }
}

// ---------------- folded filters -------------------------------------------------
__device__ __forceinline__ float fold_H(const float* __restrict__ h3,
                                        const float sv[4], int a, int b)
{
    float c0 = (a == 0 && b == 0) ? 1.f : 0.f;
    float c1 = (a < 2 && b < 2) ? sv[a * 2 + b] : 0.f;
    float c2 = 0.f;
    #pragma unroll
    for (int a1 = 0; a1 < 2; a1++)
        #pragma unroll
        for (int b1 = 0; b1 < 2; b1++) {
            int a2 = a - a1, b2 = b - b1;
            if (a2 >= 0 && a2 < 2 && b2 >= 0 && b2 < 2)
                c2 += sv[a1 * 2 + b1] * sv[a2 * 2 + b2];
        }
    return h3[0] * c0 + h3[1] * c1 + h3[2] * c2;
}

// ---------------- encoder combine (+maxpool+relu), 4-source-tau form -------------
// Each distinct source tau in {2tp-2 .. 2tp+1} is loaded ONCE and feeds both
// pool slots: acc0 (tau=2tp) with a=2-tt, acc1 (tau=2tp+1) with a=3-tt.
template <int CI, int CO, int OT, bool G0CG>
__device__ void combine_enc(const float* __restrict__ G0, int g0sT, int g0sI, int g0sN,
                            const float* __restrict__ G1, const float* __restrict__ G2,
                            const float* __restrict__ h, const float* __restrict__ sp,
                            float* __restrict__ out, int t, int tp, int ob, float* Hs)
{
    const int tid = threadIdx.x;
    const float sv[4] = { sp[0], sp[1], sp[2], sp[3] };
    for (int idx = tid; idx < CI * 9 * OT; idx += 256) {
        int oo = idx % OT;
        int tmp = idx / OT;
        int b = tmp % 3, a = (tmp / 3) % 3, i = tmp / 9;
        Hs[idx] = fold_H(&h[((ob + oo) * CI + i) * 3], sv, a, b);
    }
    __syncthreads();
    if (tid < NN) {
        const int n = tid;
        float acc0[OT], acc1[OT];
        #pragma unroll
        for (int o = 0; o < OT; o++) { acc0[o] = 0.f; acc1[o] = 0.f; }
        #pragma unroll
        for (int tt = 0; tt < 4; tt++) {
            int src = 2 * tp - 2 + tt;
            if (src < 0) src += t;
            #pragma unroll
            for (int i = 0; i < CI; i++) {
                const float* p0 = &G0[src * g0sT + i * g0sI + n * g0sN];
                float v0 = G0CG ? __ldcg(p0) : *p0;
                float v1 = __ldcg(&G1[(src * CI + i) * NN + n]);
                float v2 = __ldcg(&G2[(src * CI + i) * NN + n]);
                if (tt <= 2) {
                    const float* Hp = &Hs[(i * 3 + (2 - tt)) * 3 * OT];
                    #pragma unroll
                    for (int o = 0; o < OT; o++)
                        acc0[o] += Hp[o] * v0 + Hp[OT + o] * v1 + Hp[2 * OT + o] * v2;
                }
                if (tt >= 1) {
                    const float* Hp = &Hs[(i * 3 + (3 - tt)) * 3 * OT];
                    #pragma unroll
                    for (int o = 0; o < OT; o++)
                        acc1[o] += Hp[o] * v0 + Hp[OT + o] * v1 + Hp[2 * OT + o] * v2;
                }
            }
        }
        #pragma unroll
        for (int o = 0; o < OT; o++)
            out[(tp * CO + ob + o) * NN + n] = fmaxf(fmaxf(acc0[o], acc1[o]), 0.f);
    }
}

// ---------------- decoder combine (zero-stuffed input at half time res) ----------
template <int CI, int CO, int OT, bool RELU, bool FINAL>
__device__ void combine_dec(const float* __restrict__ G0, const float* __restrict__ G1,
                            const float* __restrict__ G2,
                            const float* __restrict__ h, const float* __restrict__ sp,
                            float* __restrict__ out, int t, int tau, int ob, float* Hs)
{
    const int tid = threadIdx.x;
    const float sv[4] = { sp[0], sp[1], sp[2], sp[3] };
    for (int idx = tid; idx < CI * 9 * OT; idx += 256) {
        int oo = idx % OT;
        int tmp = idx / OT;
        int b = tmp % 3, a = (tmp / 3) % 3, i = tmp / 9;
        Hs[idx] = fold_H(&h[((ob + oo) * CI + i) * 3], sv, a, b);
    }
    __syncthreads();
    if (tid < NN) {
        const int n = tid;
        float acc[OT];
        #pragma unroll
        for (int o = 0; o < OT; o++) acc[o] = 0.f;
        #pragma unroll
        for (int a = 0; a < 3; a++) {
            int src = tau - a; if (src < 0) src += t;
            if (src & 1) continue;             // zero-stuffed upsample
            int tl = src >> 1;
            #pragma unroll
            for (int i = 0; i < CI; i++) {
                float v0 = __ldcg(&G0[(tl * CI + i) * NN + n]);
                float v1 = __ldcg(&G1[(tl * CI + i) * NN + n]);
                float v2 = __ldcg(&G2[(tl * CI + i) * NN + n]);
                const float* Hp = &Hs[(i * 3 + a) * 3 * OT];
                #pragma unroll
                for (int o = 0; o < OT; o++)
                    acc[o] += Hp[o] * v0 + Hp[OT + o] * v1 + Hp[2 * OT + o] * v2;
            }
        }
        if (FINAL) {
            out[n * t + tau] = acc[0];         // inversevec -> (N, T)
        } else {
            #pragma unroll
            for (int o = 0; o < OT; o++) {
                float v = acc[o];
                if (RELU) v = fmaxf(v, 0.f);
                out[(tau * CO + ob + o) * NN + n] = v;
            }
        }
    }
}

// ---------------- persistent mega-kernel ----------------------------------------
__global__ __launch_bounds__(256, 1) void mega(
    const float* __restrict__ X,    const float* __restrict__ Sg,
    const float* __restrict__ s,    const float* __restrict__ h_e1,
    const float* __restrict__ h_e2, const float* __restrict__ h_d1,
    const float* __restrict__ h_d2, float* __restrict__ out)
{
    __shared__ float As[NN * ASP];   // 26.1 KB
    __shared__ float Bs[96 * BSP];   // 13.1 KB
    __shared__ float Hs[1152];       //  4.6 KB

    const int bid = blockIdx.x;

    // S0: Sg2 tiles (0-35) + P = Sg@X (36-41)
    if (bid < 36)
        gemm_stage(Sg, false, Sg, 1, (bid / 6) * 32, g_Sg2, true, (bid % 6) * 32, As, Bs);
    else if (bid < 42)
        gemm_stage(Sg, false, X, 2, 0, g_G1, false, (bid - 36) * 32, As, Bs);
    grid_barrier();

    // S1: G2_e1 = Sg @ P (P in act layout)
    if (bid < 6)
        gemm_stage(Sg, false, g_G1, 0, 0, g_G2, false, bid * 32, As, Bs);
    grid_barrier();

    // S2: combine e1 -> actA [16t x 16c x 192n]
    if (bid < 16)
        combine_enc<1, 16, 16, false>(X, 1, 0, TT, g_G1, g_G2, h_e1, s,
                                      g_actA, TT, bid, 0, Hs);
    grid_barrier();

    // S3: e2 GEMMs (96 blocks), J=256, B = actA
    {
        int mat = bid / 48, mb = bid % 6, jb = (bid % 48) / 6;
        gemm_stage(mat ? g_Sg2 : Sg, mat != 0, g_actA, 0, jb * 32,
                   mat ? g_G2 : g_G1, false, mb * 32, As, Bs);
    }
    grid_barrier();

    // S4: combine e2 -> actB [8t x 32c x 192n]
    if (bid < 64)
        combine_enc<16, 32, 4, true>(g_actA, 16 * NN, NN, 1, g_G1, g_G2, h_e2, s,
                                     g_actB, 16, bid & 7, (bid >> 3) * 4, Hs);
    grid_barrier();

    // S5: d1 GEMMs, B = actB
    {
        int mat = bid / 48, mb = bid % 6, jb = (bid % 48) / 6;
        gemm_stage(mat ? g_Sg2 : Sg, mat != 0, g_actB, 0, jb * 32,
                   mat ? g_G2 : g_G1, false, mb * 32, As, Bs);
    }
    grid_barrier();

    // S6: combine d1 -> actA [16t x 16c x 192n]
    if (bid < 64)
        combine_dec<32, 16, 4, true, false>(g_actB, g_G1, g_G2, h_d1, s,
                                            g_actA, 16, bid & 15, (bid >> 4) * 4, Hs);
    grid_barrier();

    // S7: d2 GEMMs, B = actA
    {
        int mat = bid / 48, mb = bid % 6, jb = (bid % 48) / 6;
        gemm_stage(mat ? g_Sg2 : Sg, mat != 0, g_actA, 0, jb * 32,
                   mat ? g_G2 : g_G1, false, mb * 32, As, Bs);
    }
    grid_barrier();

    // S8: combine d2 -> out (N, T)
    if (bid < 32)
        combine_dec<16, 1, 1, false, true>(g_actA, g_G1, g_G2, h_d2, s,
                                           out, TT, bid, 0, Hs);
}

// ---------------- launch ---------------------------------------------------------
extern "C" void kernel_launch(void* const* d_in, const int* in_sizes, int n_in,
                              void* d_out, int out_size)
{
    const float* X    = (const float*)d_in[0];
    const float* Sg   = (const float*)d_in[1];
    const float* s    = (const float*)d_in[2];
    const float* h_e1 = (const float*)d_in[3];
    const float* h_e2 = (const float*)d_in[4];
    const float* h_d1 = (const float*)d_in[5];
    const float* h_d2 = (const float*)d_in[6];
    float* out = (float*)d_out;

    mega<<<NB, 256>>>(X, Sg, s, h_e1, h_e2, h_d1, h_d2, out);
}

// round 4
// speedup vs baseline: 1.2003x; 1.0609x over previous
#include <cuda_runtime.h>

// GTConvAE — fused persistent kernel, R4.
// Kronecker identity: S^k x[tau] = sum_{a,b<3} c_k[a][b] * Sg^b x[(tau-a) mod t],
// c_0=delta, c_1=s, c_2=s*s. Layer = two GEMMs (Sg@act, Sg2@act) + 9-term combine
// with folded filters H[o][i][a][b]. Encoder fuses maxpool+relu; decoder exploits
// zero-stuffed upsampling. All cross-stage data flows through L2 via __ldcg /
// plain STG (write-through), so the grid barrier only needs acq/rel ordering —
// no full __threadfence (which emits CCTL.IVALL = L1 flush on sm_103a).

#define NN  192
#define TT  32
#define NB  96
#define ASP 34    // smem k-row stride for A [k][m]
#define BSP 34    // smem k-row stride for B [k][j]

// ---------------- scratch --------------------------------------------------------
__device__ float g_Sg2 [NN * NN];
__device__ float g_G1  [256 * NN];   // also holds P = Sg@X for layer e1
__device__ float g_G2  [256 * NN];
__device__ float g_actA[256 * NN];
__device__ float g_actB[256 * NN];
__device__ unsigned g_cnt = 0;
__device__ unsigned g_gen = 0;

// ---------------- grid barrier: release-arrive / acquire-poll, no L1 flush -------
__device__ __forceinline__ void grid_barrier()
{
    __syncthreads();
    if (threadIdx.x == 0) {
        unsigned gen;
        asm volatile("ld.relaxed.gpu.u32 %0, [%1];"
                     : "=r"(gen) : "l"(&g_gen) : "memory");
        unsigned prev;
        asm volatile("atom.release.gpu.add.u32 %0, [%1], %2;"
                     : "=r"(prev) : "l"(&g_cnt), "r"(1u) : "memory");
        if (prev == NB - 1) {
            asm volatile("st.relaxed.gpu.u32 [%0], %1;"
                         :: "l"(&g_cnt), "r"(0u) : "memory");
            asm volatile("st.release.gpu.u32 [%0], %1;"
                         :: "l"(&g_gen), "r"(gen + 1u) : "memory");
        } else {
            unsigned cur;
            do {
                __nanosleep(32);
                asm volatile("ld.acquire.gpu.u32 %0, [%1];"
                             : "=r"(cur) : "l"(&g_gen) : "memory");
            } while (cur == gen);
        }
    }
    __syncthreads();
}

// ---------------- GEMM stage: C = A(192x192) @ B(192xJ), one 32x32 tile ----------
// smem k-major: As[k][m], Bs[k][j] -> A reads broadcast, B reads 128B/warp.
// bmode: 0 = act layout [j*192+k] (ldcg), 1 = Sg cols [k*192+j0+j], 2 = X [k*32+j]
__device__ __noinline__ void gemm_stage(const float* __restrict__ A, bool a_cg,
                                        const float* __restrict__ Bg, int bmode, int j0,
                                        float* __restrict__ C, bool c_row, int m0,
                                        float* As, float* Bs)
{
    const int tid = threadIdx.x;
    const int tx = tid & 15, ty = tid >> 4;

    // A band 32m x 192k -> As[k][m]
    #pragma unroll
    for (int r = 0; r < 24; r++) {
        int idx = tid + 256 * r;
        int ml = idx / NN, q = idx - ml * NN;
        const float* p = &A[(m0 + ml) * NN + q];
        As[q * ASP + ml] = a_cg ? __ldcg(p) : *p;
    }

    float acc00 = 0.f, acc01 = 0.f, acc10 = 0.f, acc11 = 0.f;
    #pragma unroll
    for (int c = 0; c < 2; c++) {
        if (bmode == 0) {
            #pragma unroll
            for (int r = 0; r < 12; r++) {
                int idx = tid + 256 * r;
                int jl = idx / 96, q = idx - jl * 96;
                Bs[q * BSP + jl] = __ldcg(&Bg[(j0 + jl) * NN + 96 * c + q]);
            }
        } else if (bmode == 1) {
            #pragma unroll
            for (int r = 0; r < 12; r++) {
                int idx = tid + 256 * r;
                int kk = idx >> 5, jl = idx & 31;
                Bs[kk * BSP + jl] = Bg[(96 * c + kk) * NN + j0 + jl];
            }
        } else {
            #pragma unroll
            for (int r = 0; r < 12; r++) {
                int idx = tid + 256 * r;
                int kk = idx >> 5, jl = idx & 31;
                Bs[kk * BSP + jl] = Bg[(96 * c + kk) * TT + jl];
            }
        }
        __syncthreads();
        const float* ap = As + 96 * c * ASP + 2 * ty;
        const float* bp = Bs + 2 * tx;
        #pragma unroll 8
        for (int kk = 0; kk < 96; kk++) {
            float2 a = *(const float2*)(ap + kk * ASP);
            float2 b = *(const float2*)(bp + kk * BSP);
            acc00 += a.x * b.x; acc01 += a.x * b.y;
            acc10 += a.y * b.x; acc11 += a.y * b.y;
        }
        __syncthreads();
    }
    const int m = m0 + 2 * ty, j = j0 + 2 * tx;
    if (c_row) {
        C[(m    ) * NN + j] = acc00; C[(m    ) * NN + j + 1] = acc01;
        C[(m + 1) * NN + j] = acc10; C[(m + 1) * NN + j + 1] = acc11;
    } else {                             // [j*192 + m]
        C[(j    ) * NN + m] = acc00; C[(j + 1) * NN + m] = acc01;
        C[(j    ) * NN + m + 1] = acc10; C[(j + 1) * NN + m + 1] = acc11;
    }
}

// ---------------- folded filters -------------------------------------------------
__device__ __forceinline__ float fold_H(const float* __restrict__ h3,
                                        const float sv[4], int a, int b)
{
    float c0 = (a == 0 && b == 0) ? 1.f : 0.f;
    float c1 = (a < 2 && b < 2) ? sv[a * 2 + b] : 0.f;
    float c2 = 0.f;
    #pragma unroll
    for (int a1 = 0; a1 < 2; a1++)
        #pragma unroll
        for (int b1 = 0; b1 < 2; b1++) {
            int a2 = a - a1, b2 = b - b1;
            if (a2 >= 0 && a2 < 2 && b2 >= 0 && b2 < 2)
                c2 += sv[a1 * 2 + b1] * sv[a2 * 2 + b2];
        }
    return h3[0] * c0 + h3[1] * c1 + h3[2] * c2;
}

// ---------------- encoder combine (+maxpool+relu), 4-source-tau form -------------
template <int CI, int CO, int OT, bool G0CG>
__device__ __noinline__ void combine_enc(
    const float* __restrict__ G0, int g0sT, int g0sI, int g0sN,
    const float* __restrict__ G1, const float* __restrict__ G2,
    const float* __restrict__ h, const float* __restrict__ sp,
    float* __restrict__ out, int t, int tp, int ob, float* Hs)
{
    const int tid = threadIdx.x;
    const float sv[4] = { sp[0], sp[1], sp[2], sp[3] };
    for (int idx = tid; idx < CI * 9 * OT; idx += 256) {
        int oo = idx % OT;
        int tmp = idx / OT;
        int b = tmp % 3, a = (tmp / 3) % 3, i = tmp / 9;
        Hs[idx] = fold_H(&h[((ob + oo) * CI + i) * 3], sv, a, b);
    }
    __syncthreads();
    if (tid < NN) {
        const int n = tid;
        float acc0[OT], acc1[OT];
        #pragma unroll
        for (int o = 0; o < OT; o++) { acc0[o] = 0.f; acc1[o] = 0.f; }
        #pragma unroll
        for (int tt = 0; tt < 4; tt++) {
            int src = 2 * tp - 2 + tt;
            if (src < 0) src += t;
            #pragma unroll 8
            for (int i = 0; i < CI; i++) {
                const float* p0 = &G0[src * g0sT + i * g0sI + n * g0sN];
                float v0 = G0CG ? __ldcg(p0) : *p0;
                float v1 = __ldcg(&G1[(src * CI + i) * NN + n]);
                float v2 = __ldcg(&G2[(src * CI + i) * NN + n]);
                if (tt <= 2) {
                    const float* Hp = &Hs[(i * 3 + (2 - tt)) * 3 * OT];
                    #pragma unroll
                    for (int o = 0; o < OT; o++)
                        acc0[o] += Hp[o] * v0 + Hp[OT + o] * v1 + Hp[2 * OT + o] * v2;
                }
                if (tt >= 1) {
                    const float* Hp = &Hs[(i * 3 + (3 - tt)) * 3 * OT];
                    #pragma unroll
                    for (int o = 0; o < OT; o++)
                        acc1[o] += Hp[o] * v0 + Hp[OT + o] * v1 + Hp[2 * OT + o] * v2;
                }
            }
        }
        #pragma unroll
        for (int o = 0; o < OT; o++)
            out[(tp * CO + ob + o) * NN + n] = fmaxf(fmaxf(acc0[o], acc1[o]), 0.f);
    }
}

// ---------------- decoder combine (zero-stuffed input at half time res) ----------
template <int CI, int CO, int OT, bool RELU, bool FINAL>
__device__ __noinline__ void combine_dec(
    const float* __restrict__ G0, const float* __restrict__ G1,
    const float* __restrict__ G2,
    const float* __restrict__ h, const float* __restrict__ sp,
    float* __restrict__ out, int t, int tau, int ob, float* Hs)
{
    const int tid = threadIdx.x;
    const float sv[4] = { sp[0], sp[1], sp[2], sp[3] };
    for (int idx = tid; idx < CI * 9 * OT; idx += 256) {
        int oo = idx % OT;
        int tmp = idx / OT;
        int b = tmp % 3, a = (tmp / 3) % 3, i = tmp / 9;
        Hs[idx] = fold_H(&h[((ob + oo) * CI + i) * 3], sv, a, b);
    }
    __syncthreads();
    if (tid < NN) {
        const int n = tid;
        float acc[OT];
        #pragma unroll
        for (int o = 0; o < OT; o++) acc[o] = 0.f;
        #pragma unroll
        for (int a = 0; a < 3; a++) {
            int src = tau - a; if (src < 0) src += t;
            if (src & 1) continue;             // zero-stuffed upsample
            int tl = src >> 1;
            #pragma unroll 8
            for (int i = 0; i < CI; i++) {
                float v0 = __ldcg(&G0[(tl * CI + i) * NN + n]);
                float v1 = __ldcg(&G1[(tl * CI + i) * NN + n]);
                float v2 = __ldcg(&G2[(tl * CI + i) * NN + n]);
                const float* Hp = &Hs[(i * 3 + a) * 3 * OT];
                #pragma unroll
                for (int o = 0; o < OT; o++)
                    acc[o] += Hp[o] * v0 + Hp[OT + o] * v1 + Hp[2 * OT + o] * v2;
            }
        }
        if (FINAL) {
            out[n * t + tau] = acc[0];         // inversevec -> (N, T)
        } else {
            #pragma unroll
            for (int o = 0; o < OT; o++) {
                float v = acc[o];
                if (RELU) v = fmaxf(v, 0.f);
                out[(tau * CO + ob + o) * NN + n] = v;
            }
        }
    }
}

// ---------------- persistent mega-kernel ----------------------------------------
__global__ __launch_bounds__(256, 1) void mega(
    const float* __restrict__ X,    const float* __restrict__ Sg,
    const float* __restrict__ s,    const float* __restrict__ h_e1,
    const float* __restrict__ h_e2, const float* __restrict__ h_d1,
    const float* __restrict__ h_d2, float* __restrict__ out)
{
    __shared__ float As[NN * ASP];
    __shared__ float Bs[96 * BSP];
    __shared__ float Hs[1152];

    const int bid = blockIdx.x;

    // S0: Sg2 tiles (0-35) + P = Sg@X (36-41)
    if (bid < 36)
        gemm_stage(Sg, false, Sg, 1, (bid / 6) * 32, g_Sg2, true, (bid % 6) * 32, As, Bs);
    else if (bid < 42)
        gemm_stage(Sg, false, X, 2, 0, g_G1, false, (bid - 36) * 32, As, Bs);
    grid_barrier();

    // S1: G2_e1 = Sg @ P (P in act layout)
    if (bid < 6)
        gemm_stage(Sg, false, g_G1, 0, 0, g_G2, false, bid * 32, As, Bs);
    grid_barrier();

    // S2: combine e1 -> actA [16t x 16c x 192n]  (64 blocks)
    if (bid < 64)
        combine_enc<1, 16, 4, false>(X, 1, 0, TT, g_G1, g_G2, h_e1, s,
                                     g_actA, TT, bid & 15, (bid >> 4) * 4, Hs);
    grid_barrier();

    // S3: e2 GEMMs (96 blocks), J=256, B = actA
    {
        int mat = bid / 48, mb = bid % 6, jb = (bid % 48) / 6;
        gemm_stage(mat ? g_Sg2 : Sg, mat != 0, g_actA, 0, jb * 32,
                   mat ? g_G2 : g_G1, false, mb * 32, As, Bs);
    }
    grid_barrier();

    // S4: combine e2 -> actB [8t x 32c x 192n]
    if (bid < 64)
        combine_enc<16, 32, 4, true>(g_actA, 16 * NN, NN, 1, g_G1, g_G2, h_e2, s,
                                     g_actB, 16, bid & 7, (bid >> 3) * 4, Hs);
    grid_barrier();

    // S5: d1 GEMMs, B = actB
    {
        int mat = bid / 48, mb = bid % 6, jb = (bid % 48) / 6;
        gemm_stage(mat ? g_Sg2 : Sg, mat != 0, g_actB, 0, jb * 32,
                   mat ? g_G2 : g_G1, false, mb * 32, As, Bs);
    }
    grid_barrier();

    // S6: combine d1 -> actA [16t x 16c x 192n]
    if (bid < 64)
        combine_dec<32, 16, 4, true, false>(g_actB, g_G1, g_G2, h_d1, s,
                                            g_actA, 16, bid & 15, (bid >> 4) * 4, Hs);
    grid_barrier();

    // S7: d2 GEMMs, B = actA
    {
        int mat = bid / 48, mb = bid % 6, jb = (bid % 48) / 6;
        gemm_stage(mat ? g_Sg2 : Sg, mat != 0, g_actA, 0, jb * 32,
                   mat ? g_G2 : g_G1, false, mb * 32, As, Bs);
    }
    grid_barrier();

    // S8: combine d2 -> out (N, T)
    if (bid < 32)
        combine_dec<16, 1, 1, false, true>(g_actA, g_G1, g_G2, h_d2, s,
                                           out, TT, bid, 0, Hs);
}

// ---------------- launch ---------------------------------------------------------
extern "C" void kernel_launch(void* const* d_in, const int* in_sizes, int n_in,
                              void* d_out, int out_size)
{
    const float* X    = (const float*)d_in[0];
    const float* Sg   = (const float*)d_in[1];
    const float* s    = (const float*)d_in[2];
    const float* h_e1 = (const float*)d_in[3];
    const float* h_e2 = (const float*)d_in[4];
    const float* h_d1 = (const float*)d_in[5];
    const float* h_d2 = (const float*)d_in[6];
    float* out = (float*)d_out;

    mega<<<NB, 256>>>(X, Sg, s, h_e1, h_e2, h_d1, h_d2, out);
}

// round 5
// speedup vs baseline: 1.3635x; 1.1359x over previous
#include <cuda_runtime.h>

// GTConvAE — fused persistent kernel, R5.
// Kronecker identity: S^k x[tau] = sum_{a,b<3} c_k[a][b] * Sg^b x[(tau-a) mod t],
// c_0=delta, c_1=s, c_2=s*s. Layer = two GEMMs (Sg@act, Sg2@act) + 9-term combine
// with folded filters H[o][i][a][b]. Encoder fuses maxpool+relu; decoder exploits
// zero-stuffed upsampling. Cross-stage data via L2 (__ldcg / STG); barrier is
// acq/rel only (no CCTL.IVALL). R5: register-staged double-buffered GEMM chunks,
// fully-unrolled combine load batches, float2 C stores.

#define NN  192
#define TT  32
#define NB  96
#define ASP 34    // smem k-row stride (96 k-rows per chunk)
#define BSP 34

// ---------------- scratch --------------------------------------------------------
__device__ float g_Sg2 [NN * NN];
__device__ float g_G1  [256 * NN];   // also holds P = Sg@X for layer e1
__device__ float g_G2  [256 * NN];
__device__ float g_actA[256 * NN];
__device__ float g_actB[256 * NN];
__device__ unsigned g_cnt = 0;
__device__ unsigned g_gen = 0;

// ---------------- grid barrier: release-arrive / acquire-poll --------------------
__device__ __forceinline__ void grid_barrier()
{
    __syncthreads();
    if (threadIdx.x == 0) {
        unsigned gen;
        asm volatile("ld.relaxed.gpu.u32 %0, [%1];"
                     : "=r"(gen) : "l"(&g_gen) : "memory");
        unsigned prev;
        asm volatile("atom.release.gpu.add.u32 %0, [%1], %2;"
                     : "=r"(prev) : "l"(&g_cnt), "r"(1u) : "memory");
        if (prev == NB - 1) {
            asm volatile("st.relaxed.gpu.u32 [%0], %1;"
                         :: "l"(&g_cnt), "r"(0u) : "memory");
            asm volatile("st.release.gpu.u32 [%0], %1;"
                         :: "l"(&g_gen), "r"(gen + 1u) : "memory");
        } else {
            unsigned cur;
            do {
                __nanosleep(16);
                asm volatile("ld.acquire.gpu.u32 %0, [%1];"
                             : "=r"(cur) : "l"(&g_gen) : "memory");
            } while (cur == gen);
        }
    }
    __syncthreads();
}

// ---------------- GEMM stage: C = A(192x192) @ B(192xJ), one 32x32 tile ----------
// K split into two 96-chunks; chunk1 A/B prefetched into registers while chunk0
// computes (removes the exposed mid-stage LDG wave). smem k-major: As[k][m],
// Bs[k][j]. BMODE: 0 = act [j*192+k], 1 = Sg cols [k*192+j0+j], 2 = X [k*32+j].
template <int BMODE, bool ACG, bool CROW>
__device__ __noinline__ void gemm_stage(const float* __restrict__ A,
                                        const float* __restrict__ Bg, int j0,
                                        float* __restrict__ C, int m0,
                                        float* As, float* Bs)
{
    const int tid = threadIdx.x;
    const int tx = tid & 15, ty = tid >> 4;

    float ra[12], rb[12];

    // ---- fetch chunk (kbase) into registers ----
    auto fetch = [&](int kbase) {
        #pragma unroll
        for (int r = 0; r < 12; r++) {
            int idx = tid + 256 * r;
            int ml = idx / 96, q = idx - ml * 96;       // A: m-local, k-local
            const float* p = &A[(m0 + ml) * NN + kbase + q];
            ra[r] = ACG ? __ldcg(p) : *p;
        }
        #pragma unroll
        for (int r = 0; r < 12; r++) {
            int idx = tid + 256 * r;
            if (BMODE == 0) {
                int jl = idx / 96, q = idx - jl * 96;
                rb[r] = __ldcg(&Bg[(j0 + jl) * NN + kbase + q]);
            } else if (BMODE == 1) {
                int kk = idx >> 5, jl = idx & 31;
                rb[r] = Bg[(kbase + kk) * NN + j0 + jl];
            } else {
                int kk = idx >> 5, jl = idx & 31;
                rb[r] = Bg[(kbase + kk) * TT + jl];
            }
        }
    };
    auto stage = [&]() {
        #pragma unroll
        for (int r = 0; r < 12; r++) {
            int idx = tid + 256 * r;
            int ml = idx / 96, q = idx - ml * 96;
            As[q * ASP + ml] = ra[r];
        }
        #pragma unroll
        for (int r = 0; r < 12; r++) {
            int idx = tid + 256 * r;
            if (BMODE == 0) {
                int jl = idx / 96, q = idx - jl * 96;
                Bs[q * BSP + jl] = rb[r];
            } else {
                int kk = idx >> 5, jl = idx & 31;
                Bs[kk * BSP + jl] = rb[r];
            }
        }
    };

    float acc00 = 0.f, acc01 = 0.f, acc10 = 0.f, acc11 = 0.f;
    const float* ap = As + 2 * ty;
    const float* bp = Bs + 2 * tx;

    fetch(0);
    stage();
    __syncthreads();
    fetch(96);                      // in flight during chunk-0 compute
    #pragma unroll 8
    for (int kk = 0; kk < 96; kk++) {
        float2 a = *(const float2*)(ap + kk * ASP);
        float2 b = *(const float2*)(bp + kk * BSP);
        acc00 += a.x * b.x; acc01 += a.x * b.y;
        acc10 += a.y * b.x; acc11 += a.y * b.y;
    }
    __syncthreads();
    stage();
    __syncthreads();
    #pragma unroll 8
    for (int kk = 0; kk < 96; kk++) {
        float2 a = *(const float2*)(ap + kk * ASP);
        float2 b = *(const float2*)(bp + kk * BSP);
        acc00 += a.x * b.x; acc01 += a.x * b.y;
        acc10 += a.y * b.x; acc11 += a.y * b.y;
    }

    const int m = m0 + 2 * ty, j = j0 + 2 * tx;
    if (CROW) {                           // C[m][j], j pair contiguous
        *(float2*)&C[(m    ) * NN + j] = make_float2(acc00, acc01);
        *(float2*)&C[(m + 1) * NN + j] = make_float2(acc10, acc11);
    } else {                              // C[j][m], m pair contiguous
        *(float2*)&C[(j    ) * NN + m] = make_float2(acc00, acc10);
        *(float2*)&C[(j + 1) * NN + m] = make_float2(acc01, acc11);
    }
}

// ---------------- folded filters -------------------------------------------------
__device__ __forceinline__ float fold_H(const float* __restrict__ h3,
                                        const float sv[4], int a, int b)
{
    float c0 = (a == 0 && b == 0) ? 1.f : 0.f;
    float c1 = (a < 2 && b < 2) ? sv[a * 2 + b] : 0.f;
    float c2 = 0.f;
    #pragma unroll
    for (int a1 = 0; a1 < 2; a1++)
        #pragma unroll
        for (int b1 = 0; b1 < 2; b1++) {
            int a2 = a - a1, b2 = b - b1;
            if (a2 >= 0 && a2 < 2 && b2 >= 0 && b2 < 2)
                c2 += sv[a1 * 2 + b1] * sv[a2 * 2 + b2];
        }
    return h3[0] * c0 + h3[1] * c1 + h3[2] * c2;
}

// ---------------- encoder combine (+maxpool+relu), 4-source-tau form -------------
template <int CI, int CO, int OT, bool G0CG>
__device__ __noinline__ void combine_enc(
    const float* __restrict__ G0, int g0sT, int g0sI, int g0sN,
    const float* __restrict__ G1, const float* __restrict__ G2,
    const float* __restrict__ h, const float* __restrict__ sp,
    float* __restrict__ out, int t, int tp, int ob, float* Hs)
{
    const int tid = threadIdx.x;
    const float sv[4] = { sp[0], sp[1], sp[2], sp[3] };
    for (int idx = tid; idx < CI * 9 * OT; idx += 256) {
        int oo = idx % OT;
        int tmp = idx / OT;
        int b = tmp % 3, a = (tmp / 3) % 3, i = tmp / 9;
        Hs[idx] = fold_H(&h[((ob + oo) * CI + i) * 3], sv, a, b);
    }
    __syncthreads();
    if (tid < NN) {
        const int n = tid;
        float acc0[OT], acc1[OT];
        #pragma unroll
        for (int o = 0; o < OT; o++) { acc0[o] = 0.f; acc1[o] = 0.f; }
        #pragma unroll
        for (int tt = 0; tt < 4; tt++) {
            int src = 2 * tp - 2 + tt;
            if (src < 0) src += t;
            #pragma unroll
            for (int i = 0; i < CI; i++) {
                const float* p0 = &G0[src * g0sT + i * g0sI + n * g0sN];
                float v0 = G0CG ? __ldcg(p0) : *p0;
                float v1 = __ldcg(&G1[(src * CI + i) * NN + n]);
                float v2 = __ldcg(&G2[(src * CI + i) * NN + n]);
                if (tt <= 2) {
                    const float* Hp = &Hs[(i * 3 + (2 - tt)) * 3 * OT];
                    #pragma unroll
                    for (int o = 0; o < OT; o++)
                        acc0[o] += Hp[o] * v0 + Hp[OT + o] * v1 + Hp[2 * OT + o] * v2;
                }
                if (tt >= 1) {
                    const float* Hp = &Hs[(i * 3 + (3 - tt)) * 3 * OT];
                    #pragma unroll
                    for (int o = 0; o < OT; o++)
                        acc1[o] += Hp[o] * v0 + Hp[OT + o] * v1 + Hp[2 * OT + o] * v2;
                }
            }
        }
        #pragma unroll
        for (int o = 0; o < OT; o++)
            out[(tp * CO + ob + o) * NN + n] = fmaxf(fmaxf(acc0[o], acc1[o]), 0.f);
    }
}

// ---------------- decoder combine (zero-stuffed input at half time res) ----------
template <int CI, int CO, int OT, bool RELU, bool FINAL>
__device__ __noinline__ void combine_dec(
    const float* __restrict__ G0, const float* __restrict__ G1,
    const float* __restrict__ G2,
    const float* __restrict__ h, const float* __restrict__ sp,
    float* __restrict__ out, int t, int tau, int ob, float* Hs)
{
    const int tid = threadIdx.x;
    const float sv[4] = { sp[0], sp[1], sp[2], sp[3] };
    for (int idx = tid; idx < CI * 9 * OT; idx += 256) {
        int oo = idx % OT;
        int tmp = idx / OT;
        int b = tmp % 3, a = (tmp / 3) % 3, i = tmp / 9;
        Hs[idx] = fold_H(&h[((ob + oo) * CI + i) * 3], sv, a, b);
    }
    __syncthreads();
    if (tid < NN) {
        const int n = tid;
        float acc[OT];
        #pragma unroll
        for (int o = 0; o < OT; o++) acc[o] = 0.f;
        #pragma unroll
        for (int a = 0; a < 3; a++) {
            int src = tau - a; if (src < 0) src += t;
            if (src & 1) continue;             // zero-stuffed upsample
            int tl = src >> 1;
            #pragma unroll 16
            for (int i = 0; i < CI; i++) {
                float v0 = __ldcg(&G0[(tl * CI + i) * NN + n]);
                float v1 = __ldcg(&G1[(tl * CI + i) * NN + n]);
                float v2 = __ldcg(&G2[(tl * CI + i) * NN + n]);
                const float* Hp = &Hs[(i * 3 + a) * 3 * OT];
                #pragma unroll
                for (int o = 0; o < OT; o++)
                    acc[o] += Hp[o] * v0 + Hp[OT + o] * v1 + Hp[2 * OT + o] * v2;
            }
        }
        if (FINAL) {
            out[n * t + tau] = acc[0];         // inversevec -> (N, T)
        } else {
            #pragma unroll
            for (int o = 0; o < OT; o++) {
                float v = acc[o];
                if (RELU) v = fmaxf(v, 0.f);
                out[(tau * CO + ob + o) * NN + n] = v;
            }
        }
    }
}

// ---------------- persistent mega-kernel ----------------------------------------
__global__ __launch_bounds__(256, 1) void mega(
    const float* __restrict__ X,    const float* __restrict__ Sg,
    const float* __restrict__ s,    const float* __restrict__ h_e1,
    const float* __restrict__ h_e2, const float* __restrict__ h_d1,
    const float* __restrict__ h_d2, float* __restrict__ out)
{
    __shared__ float As[96 * ASP];   // 13.1 KB
    __shared__ float Bs[96 * BSP];   // 13.1 KB
    __shared__ float Hs[1152];       //  4.6 KB

    const int bid = blockIdx.x;

    // S0: Sg2 tiles (0-35) + P = Sg@X (36-41)
    if (bid < 36)
        gemm_stage<1, false, true>(Sg, Sg, (bid / 6) * 32, g_Sg2, (bid % 6) * 32, As, Bs);
    else if (bid < 42)
        gemm_stage<2, false, false>(Sg, X, 0, g_G1, (bid - 36) * 32, As, Bs);
    grid_barrier();

    // S1: G2_e1 = Sg @ P (P in act layout)
    if (bid < 6)
        gemm_stage<0, false, false>(Sg, g_G1, 0, g_G2, bid * 32, As, Bs);
    grid_barrier();

    // S2: combine e1 -> actA [16t x 16c x 192n]  (64 blocks)
    if (bid < 64)
        combine_enc<1, 16, 4, false>(X, 1, 0, TT, g_G1, g_G2, h_e1, s,
                                     g_actA, TT, bid & 15, (bid >> 4) * 4, Hs);
    grid_barrier();

    // S3: e2 GEMMs (96 blocks), J=256, B = actA
    {
        int mb = bid % 6, j0 = ((bid % 48) / 6) * 32;
        if (bid < 48)
            gemm_stage<0, false, false>(Sg, g_actA, j0, g_G1, mb * 32, As, Bs);
        else
            gemm_stage<0, true, false>(g_Sg2, g_actA, j0, g_G2, mb * 32, As, Bs);
    }
    grid_barrier();

    // S4: combine e2 -> actB [8t x 32c x 192n]
    if (bid < 64)
        combine_enc<16, 32, 4, true>(g_actA, 16 * NN, NN, 1, g_G1, g_G2, h_e2, s,
                                     g_actB, 16, bid & 7, (bid >> 3) * 4, Hs);
    grid_barrier();

    // S5: d1 GEMMs, B = actB
    {
        int mb = bid % 6, j0 = ((bid % 48) / 6) * 32;
        if (bid < 48)
            gemm_stage<0, false, false>(Sg, g_actB, j0, g_G1, mb * 32, As, Bs);
        else
            gemm_stage<0, true, false>(g_Sg2, g_actB, j0, g_G2, mb * 32, As, Bs);
    }
    grid_barrier();

    // S6: combine d1 -> actA [16t x 16c x 192n]
    if (bid < 64)
        combine_dec<32, 16, 4, true, false>(g_actB, g_G1, g_G2, h_d1, s,
                                            g_actA, 16, bid & 15, (bid >> 4) * 4, Hs);
    grid_barrier();

    // S7: d2 GEMMs, B = actA
    {
        int mb = bid % 6, j0 = ((bid % 48) / 6) * 32;
        if (bid < 48)
            gemm_stage<0, false, false>(Sg, g_actA, j0, g_G1, mb * 32, As, Bs);
        else
            gemm_stage<0, true, false>(g_Sg2, g_actA, j0, g_G2, mb * 32, As, Bs);
    }
    grid_barrier();

    // S8: combine d2 -> out (N, T)
    if (bid < 32)
        combine_dec<16, 1, 1, false, true>(g_actA, g_G1, g_G2, h_d2, s,
                                           out, TT, bid, 0, Hs);
}

// ---------------- launch ---------------------------------------------------------
extern "C" void kernel_launch(void* const* d_in, const int* in_sizes, int n_in,
                              void* d_out, int out_size)
{
    const float* X    = (const float*)d_in[0];
    const float* Sg   = (const float*)d_in[1];
    const float* s    = (const float*)d_in[2];
    const float* h_e1 = (const float*)d_in[3];
    const float* h_e2 = (const float*)d_in[4];
    const float* h_d1 = (const float*)d_in[5];
    const float* h_d2 = (const float*)d_in[6];
    float* out = (float*)d_out;

    mega<<<NB, 256>>>(X, Sg, s, h_e1, h_e2, h_d1, h_d2, out);
}

// round 7
// speedup vs baseline: 1.4926x; 1.0947x over previous
#include <cuda_runtime.h>
#include <cstdint>

// GTConvAE — fused persistent kernel, R7 (R6 + j0 fix in the X tile load).
// Kronecker identity: S^k x[tau] = sum_{a,b<3} c_k[a][b] * Sg^b x[(tau-a) mod t].
// Layer = two GEMMs (G1=Sg@act, G2=Sg2@act) + 9-term combine with folded filters.
// Encoder fuses maxpool+relu; decoder exploits zero-stuffed upsampling.
// 192 blocks x 128 threads, cp.async tile loads (.cg for cross-stage data),
// [m][k]/[j][k] float4 smem GEMM, e1's G2 computed as an in-combine mini-GEMM.

#define NN  192
#define TT  32
#define NB  192
#define KS  196   // smem row stride in floats (16B aligned)

// ---------------- scratch --------------------------------------------------------
__device__ float g_Sg2 [NN * NN];
__device__ float g_G1  [256 * NN];   // act-layout [j][n]; also P = Sg@X for e1
__device__ float g_G2  [256 * NN];
__device__ float g_actA[256 * NN];
__device__ float g_actB[256 * NN];
__device__ unsigned g_cnt = 0;
__device__ unsigned g_gen = 0;

// ---------------- grid barrier: release-arrive / acquire-poll --------------------
__device__ __forceinline__ void grid_barrier()
{
    __syncthreads();
    if (threadIdx.x == 0) {
        unsigned gen;
        asm volatile("ld.relaxed.gpu.u32 %0, [%1];"
                     : "=r"(gen) : "l"(&g_gen) : "memory");
        unsigned prev;
        asm volatile("atom.release.gpu.add.u32 %0, [%1], %2;"
                     : "=r"(prev) : "l"(&g_cnt), "r"(1u) : "memory");
        if (prev == NB - 1) {
            asm volatile("st.relaxed.gpu.u32 [%0], %1;"
                         :: "l"(&g_cnt), "r"(0u) : "memory");
            asm volatile("st.release.gpu.u32 [%0], %1;"
                         :: "l"(&g_gen), "r"(gen + 1u) : "memory");
        } else {
            unsigned cur;
            do {
                __nanosleep(16);
                asm volatile("ld.acquire.gpu.u32 %0, [%1];"
                             : "=r"(cur) : "l"(&g_gen) : "memory");
            } while (cur == gen);
        }
    }
    __syncthreads();
}

// ---------------- cp.async helpers ----------------------------------------------
__device__ __forceinline__ void cp16(float* dst, const float* src, bool cg)
{
    uint32_t d = (uint32_t)__cvta_generic_to_shared(dst);
    if (cg)
        asm volatile("cp.async.cg.shared.global [%0], [%1], 16;" :: "r"(d), "l"(src));
    else
        asm volatile("cp.async.ca.shared.global [%0], [%1], 16;" :: "r"(d), "l"(src));
}
__device__ __forceinline__ void cp_wait_all()
{
    asm volatile("cp.async.wait_all;" ::: "memory");
}

// ---------------- GEMM: one 32m x 16j tile of C = A(192x192) @ B -----------------
// smem [m][k] / [j][k], float4 inner loop, full k=192, no mid sync.
// BMODE: 0 = act [j*NN+k] (cp .cg), 1 = Sg col-slice [k*NN+j0+j], 2 = X [k*TT+j0+j].
// CROW: true -> C[m*NN+j] (row-major, for Sg2); false -> C[j*NN+m] (act layout).
template <int BMODE, bool ACG, bool CROW>
__device__ void gemm16(const float* __restrict__ A, const float* __restrict__ Bg,
                       int j0, float* __restrict__ C, int m0,
                       float* As, float* Bs)
{
    const int tid = threadIdx.x;
    const int tx = tid & 7, ty = tid >> 3;      // j-pair, m-pair

    // A band: 32 rows x 192 k  -> As[m][k]
    #pragma unroll
    for (int r = 0; r < 12; r++) {
        int op = tid + 128 * r;
        int ml = op / 48, kq = op - ml * 48;
        cp16(&As[ml * KS + 4 * kq], &A[(m0 + ml) * NN + 4 * kq], ACG);
    }
    if (BMODE == 0) {
        #pragma unroll
        for (int r = 0; r < 6; r++) {
            int op = tid + 128 * r;
            int jl = op / 48, kq = op - jl * 48;
            cp16(&Bs[jl * KS + 4 * kq], &Bg[(j0 + jl) * NN + 4 * kq], true);
        }
        cp_wait_all();
    } else {
        cp_wait_all();
        #pragma unroll
        for (int idx = tid, r = 0; r < 24; r++, idx += 128) {
            int jl = idx & 15, kk = idx >> 4;
            Bs[jl * KS + kk] = (BMODE == 1) ? Bg[kk * NN + j0 + jl]
                                            : Bg[kk * TT + j0 + jl];
        }
    }
    __syncthreads();

    float a00 = 0.f, a01 = 0.f, a10 = 0.f, a11 = 0.f;
    const float* ap0 = As + (2 * ty) * KS;
    const float* ap1 = ap0 + KS;
    const float* bp0 = Bs + (2 * tx) * KS;
    const float* bp1 = bp0 + KS;
    #pragma unroll 8
    for (int k = 0; k < NN; k += 4) {
        float4 a0 = *(const float4*)(ap0 + k);
        float4 a1 = *(const float4*)(ap1 + k);
        float4 b0 = *(const float4*)(bp0 + k);
        float4 b1 = *(const float4*)(bp1 + k);
        a00 += a0.x * b0.x; a00 += a0.y * b0.y; a00 += a0.z * b0.z; a00 += a0.w * b0.w;
        a01 += a0.x * b1.x; a01 += a0.y * b1.y; a01 += a0.z * b1.z; a01 += a0.w * b1.w;
        a10 += a1.x * b0.x; a10 += a1.y * b0.y; a10 += a1.z * b0.z; a10 += a1.w * b0.w;
        a11 += a1.x * b1.x; a11 += a1.y * b1.y; a11 += a1.z * b1.z; a11 += a1.w * b1.w;
    }
    __syncthreads();      // Bs/As reused by later stages
    const int m = m0 + 2 * ty, j = j0 + 2 * tx;
    if (CROW) {
        *(float2*)&C[(m    ) * NN + j] = make_float2(a00, a01);
        *(float2*)&C[(m + 1) * NN + j] = make_float2(a10, a11);
    } else {
        *(float2*)&C[(j    ) * NN + m] = make_float2(a00, a10);
        *(float2*)&C[(j + 1) * NN + m] = make_float2(a01, a11);
    }
}

// ---------------- folded filters -------------------------------------------------
__device__ __forceinline__ float fold_H(const float* __restrict__ h3,
                                        const float sv[4], int a, int b)
{
    float c0 = (a == 0 && b == 0) ? 1.f : 0.f;
    float c1 = (a < 2 && b < 2) ? sv[a * 2 + b] : 0.f;
    float c2 = 0.f;
    #pragma unroll
    for (int a1 = 0; a1 < 2; a1++)
        #pragma unroll
        for (int b1 = 0; b1 < 2; b1++) {
            int a2 = a - a1, b2 = b - b1;
            if (a2 >= 0 && a2 < 2 && b2 >= 0 && b2 < 2)
                c2 += sv[a1 * 2 + b1] * sv[a2 * 2 + b2];
        }
    return h3[0] * c0 + h3[1] * c1 + h3[2] * c2;
}

__device__ __forceinline__ void build_Hs(float* Hs, const float* __restrict__ h,
                                         const float sv[4], int CI, int OT, int ob)
{
    for (int idx = threadIdx.x; idx < CI * 9 * OT; idx += 128) {
        int oo = idx % OT;
        int tmp = idx / OT;
        int b = tmp % 3, a = (tmp / 3) % 3, i = tmp / 9;
        Hs[idx] = fold_H(&h[((ob + oo) * CI + i) * 3], sv, a, b);
    }
}

// ---------------- encoder combine (e2): n-pair threads, float2 loads -------------
template <int CI, int CO, int OT>
__device__ void combine_enc2(const float* __restrict__ G0,
                             const float* __restrict__ G1,
                             const float* __restrict__ G2,
                             const float* __restrict__ h, const float* __restrict__ sp,
                             float* __restrict__ out, int t, int tp, int ob, float* Hs)
{
    const int tid = threadIdx.x;
    const float sv[4] = { sp[0], sp[1], sp[2], sp[3] };
    build_Hs(Hs, h, sv, CI, OT, ob);
    __syncthreads();
    if (tid < 96) {
        const int n2 = 2 * tid;
        float2 acc0[OT], acc1[OT];
        #pragma unroll
        for (int o = 0; o < OT; o++) {
            acc0[o] = make_float2(0.f, 0.f); acc1[o] = make_float2(0.f, 0.f);
        }
        #pragma unroll
        for (int tt = 0; tt < 4; tt++) {
            int src = (2 * tp - 2 + tt + t) & (t - 1);
            #pragma unroll
            for (int i = 0; i < CI; i++) {
                float2 v0 = __ldcg((const float2*)&G0[(src * CI + i) * NN + n2]);
                float2 v1 = __ldcg((const float2*)&G1[(src * CI + i) * NN + n2]);
                float2 v2 = __ldcg((const float2*)&G2[(src * CI + i) * NN + n2]);
                if (tt <= 2) {
                    const float* Hp = &Hs[(i * 3 + (2 - tt)) * 3 * OT];
                    #pragma unroll
                    for (int o = 0; o < OT; o++) {
                        float h0 = Hp[o], h1 = Hp[OT + o], h2 = Hp[2 * OT + o];
                        acc0[o].x += h0 * v0.x + h1 * v1.x + h2 * v2.x;
                        acc0[o].y += h0 * v0.y + h1 * v1.y + h2 * v2.y;
                    }
                }
                if (tt >= 1) {
                    const float* Hp = &Hs[(i * 3 + (3 - tt)) * 3 * OT];
                    #pragma unroll
                    for (int o = 0; o < OT; o++) {
                        float h0 = Hp[o], h1 = Hp[OT + o], h2 = Hp[2 * OT + o];
                        acc1[o].x += h0 * v0.x + h1 * v1.x + h2 * v2.x;
                        acc1[o].y += h0 * v0.y + h1 * v1.y + h2 * v2.y;
                    }
                }
            }
        }
        #pragma unroll
        for (int o = 0; o < OT; o++) {
            float2 r;
            r.x = fmaxf(fmaxf(acc0[o].x, acc1[o].x), 0.f);
            r.y = fmaxf(fmaxf(acc0[o].y, acc1[o].y), 0.f);
            *(float2*)&out[(tp * CO + ob + o) * NN + n2] = r;
        }
    }
}

// ---------------- decoder combine: zero-stuffed input, n-pair threads ------------
template <int CI, int CO, int OT>
__device__ void combine_dec2(const float* __restrict__ G0,
                             const float* __restrict__ G1,
                             const float* __restrict__ G2,
                             const float* __restrict__ h, const float* __restrict__ sp,
                             float* __restrict__ out, int t, int tau, int ob, float* Hs)
{
    const int tid = threadIdx.x;
    const float sv[4] = { sp[0], sp[1], sp[2], sp[3] };
    build_Hs(Hs, h, sv, CI, OT, ob);
    __syncthreads();
    if (tid < 96) {
        const int n2 = 2 * tid;
        float2 acc[OT];
        #pragma unroll
        for (int o = 0; o < OT; o++) acc[o] = make_float2(0.f, 0.f);
        #pragma unroll
        for (int a = 0; a < 3; a++) {
            int src = tau - a; if (src < 0) src += t;
            if (src & 1) continue;             // zero-stuffed upsample
            int tl = src >> 1;
            #pragma unroll 16
            for (int i = 0; i < CI; i++) {
                float2 v0 = __ldcg((const float2*)&G0[(tl * CI + i) * NN + n2]);
                float2 v1 = __ldcg((const float2*)&G1[(tl * CI + i) * NN + n2]);
                float2 v2 = __ldcg((const float2*)&G2[(tl * CI + i) * NN + n2]);
                const float* Hp = &Hs[(i * 3 + a) * 3 * OT];
                #pragma unroll
                for (int o = 0; o < OT; o++) {
                    float h0 = Hp[o], h1 = Hp[OT + o], h2 = Hp[2 * OT + o];
                    acc[o].x += h0 * v0.x + h1 * v1.x + h2 * v2.x;
                    acc[o].y += h0 * v0.y + h1 * v1.y + h2 * v2.y;
                }
            }
        }
        #pragma unroll
        for (int o = 0; o < OT; o++) {
            float2 r;
            r.x = fmaxf(acc[o].x, 0.f);
            r.y = fmaxf(acc[o].y, 0.f);
            *(float2*)&out[(tau * CO + ob + o) * NN + n2] = r;
        }
    }
}

// ---------------- persistent mega-kernel ----------------------------------------
__global__ __launch_bounds__(128, 1) void mega(
    const float* __restrict__ X,    const float* __restrict__ Sg,
    const float* __restrict__ s,    const float* __restrict__ h_e1,
    const float* __restrict__ h_e2, const float* __restrict__ h_d1,
    const float* __restrict__ h_d2, float* __restrict__ out)
{
    __shared__ float As[32 * KS];    // 25.1 KB
    __shared__ float Bs[16 * KS];    // 12.5 KB
    __shared__ float Hs[576];        //  2.3 KB
    __shared__ float G2s[128];       //  e1 mini-GEMM result

    const int bid = blockIdx.x;
    const int tid = threadIdx.x;

    // ======== S0: Sg2 (72 tiles) + P = Sg@X (12 tiles) ========
    if (bid < 72) {
        int jt = bid / 6, mb = bid % 6;
        gemm16<1, false, true>(Sg, Sg, jt * 16, g_Sg2, mb * 32, As, Bs);
    } else if (bid < 84) {
        int b2 = bid - 72;
        int jt = b2 / 6, mb = b2 % 6;
        gemm16<2, false, false>(Sg, X, jt * 16, g_G1, mb * 32, As, Bs);
    }
    grid_barrier();

    // ======== S2': e1 combine with fused mini-GEMM for G2 ========
    // block = (tp 0..15, nt 0..5). Computes G2[4src x 32n] = Sg[n-band] @ P[:,srcs]
    // then combine+pool+relu -> actA[16t x 16c x 192n].
    if (bid < 96) {
        const int tp = bid & 15, nt = bid >> 4;
        const int n0 = nt * 32;
        // A = Sg rows n0..n0+31
        #pragma unroll
        for (int r = 0; r < 12; r++) {
            int op = tid + 128 * r;
            int ml = op / 48, kq = op - ml * 48;
            cp16(&As[ml * KS + 4 * kq], &Sg[(n0 + ml) * NN + 4 * kq], false);
        }
        // B = P rows for the 4 source taus (.cg; written in S0)
        #pragma unroll
        for (int r = 0; r < 2; r++) {
            int op = tid + 128 * r;
            if (op < 192) {
                int ttl = op / 48, kq = op - ttl * 48;
                int src = (2 * tp - 2 + ttl + TT) & (TT - 1);
                cp16(&Bs[ttl * KS + 4 * kq], &g_G1[src * NN + 4 * kq], true);
            }
        }
        const float sv[4] = { s[0], s[1], s[2], s[3] };
        // Hs for CI=1, OT=16: Hs[(a*3+b)*16 + o]
        for (int idx = tid; idx < 144; idx += 128) {
            int o = idx & 15;
            int ab = idx >> 4;
            Hs[idx] = fold_H(&h_e1[o * 3], sv, ab / 3, ab % 3);
        }
        cp_wait_all();
        __syncthreads();
        // mini-GEMM: G2s[st][nl] = Sg[n0+nl,:] . P[src_st,:]
        {
            int nl = tid & 31, st = tid >> 5;
            float acc = 0.f;
            const float* ap = As + nl * KS;
            const float* bp = Bs + st * KS;
            #pragma unroll 12
            for (int k = 0; k < NN; k += 4) {
                float4 a = *(const float4*)(ap + k);
                float4 b = *(const float4*)(bp + k);
                acc += a.x * b.x; acc += a.y * b.y; acc += a.z * b.z; acc += a.w * b.w;
            }
            G2s[st * 32 + nl] = acc;
        }
        __syncthreads();
        // combine: thread = (nl, og), og handles 4 outputs
        {
            int nl = tid & 31, og = tid >> 5;
            int n = n0 + nl;
            float acc0[4] = {0.f, 0.f, 0.f, 0.f};
            float acc1[4] = {0.f, 0.f, 0.f, 0.f};
            #pragma unroll
            for (int ttl = 0; ttl < 4; ttl++) {
                int src = (2 * tp - 2 + ttl + TT) & (TT - 1);
                float v0 = X[n * TT + src];
                float v1 = Bs[ttl * KS + n];       // P[src][n]
                float v2 = G2s[ttl * 32 + nl];
                if (ttl <= 2) {
                    int a = 2 - ttl;
                    #pragma unroll
                    for (int oo = 0; oo < 4; oo++) {
                        int o = og * 4 + oo;
                        acc0[oo] += Hs[(a * 3 + 0) * 16 + o] * v0
                                  + Hs[(a * 3 + 1) * 16 + o] * v1
                                  + Hs[(a * 3 + 2) * 16 + o] * v2;
                    }
                }
                if (ttl >= 1) {
                    int a = 3 - ttl;
                    #pragma unroll
                    for (int oo = 0; oo < 4; oo++) {
                        int o = og * 4 + oo;
                        acc1[oo] += Hs[(a * 3 + 0) * 16 + o] * v0
                                  + Hs[(a * 3 + 1) * 16 + o] * v1
                                  + Hs[(a * 3 + 2) * 16 + o] * v2;
                    }
                }
            }
            #pragma unroll
            for (int oo = 0; oo < 4; oo++) {
                int o = og * 4 + oo;
                g_actA[(tp * 16 + o) * NN + n] = fmaxf(fmaxf(acc0[oo], acc1[oo]), 0.f);
            }
        }
    }
    grid_barrier();

    // ======== S3: e2 GEMMs, 192 tiles, B = actA ========
    {
        int mat = bid / 96, r = bid % 96;
        int mb = r / 16, jt = r % 16;
        if (mat == 0)
            gemm16<0, false, false>(Sg, g_actA, jt * 16, g_G1, mb * 32, As, Bs);
        else
            gemm16<0, true, false>(g_Sg2, g_actA, jt * 16, g_G2, mb * 32, As, Bs);
    }
    grid_barrier();

    // ======== S4: combine e2 -> actB ========
    if (bid < 128) {
        int tp = bid & 7, obg = bid >> 3;      // 16 groups of OT=2
        combine_enc2<16, 32, 2>(g_actA, g_G1, g_G2, h_e2, s,
                                g_actB, 16, tp, obg * 2, Hs);
    }
    grid_barrier();

    // ======== S5: d1 GEMMs, B = actB ========
    {
        int mat = bid / 96, r = bid % 96;
        int mb = r / 16, jt = r % 16;
        if (mat == 0)
            gemm16<0, false, false>(Sg, g_actB, jt * 16, g_G1, mb * 32, As, Bs);
        else
            gemm16<0, true, false>(g_Sg2, g_actB, jt * 16, g_G2, mb * 32, As, Bs);
    }
    grid_barrier();

    // ======== S6: combine d1 -> actA ========
    if (bid < 128) {
        int tau = bid & 15, obg = bid >> 4;    // 8 groups of OT=2
        combine_dec2<32, 16, 2>(g_actB, g_G1, g_G2, h_d1, s,
                                g_actA, 16, tau, obg * 2, Hs);
    }
    grid_barrier();

    // ======== S7: d2 GEMMs, B = actA ========
    {
        int mat = bid / 96, r = bid % 96;
        int mb = r / 16, jt = r % 16;
        if (mat == 0)
            gemm16<0, false, false>(Sg, g_actA, jt * 16, g_G1, mb * 32, As, Bs);
        else
            gemm16<0, true, false>(g_Sg2, g_actA, jt * 16, g_G2, mb * 32, As, Bs);
    }
    grid_barrier();

    // ======== S8: final combine d2 -> out (N, T) ========
    if (bid < 32) {
        const int tau = bid;
        const float sv[4] = { s[0], s[1], s[2], s[3] };
        for (int idx = tid; idx < 144; idx += 128) {   // CI=16, OT=1
            int b = idx % 3, a = (idx / 3) % 3, i = idx / 9;
            Hs[idx] = fold_H(&h_d2[i * 3], sv, a, b);
        }
        __syncthreads();
        if (tid < 96) {
            const int n2 = 2 * tid;
            float2 acc = make_float2(0.f, 0.f);
            #pragma unroll
            for (int a = 0; a < 3; a++) {
                int src = tau - a; if (src < 0) src += TT;
                if (src & 1) continue;
                int tl = src >> 1;
                #pragma unroll
                for (int i = 0; i < 16; i++) {
                    float2 v0 = __ldcg((const float2*)&g_actA[(tl * 16 + i) * NN + n2]);
                    float2 v1 = __ldcg((const float2*)&g_G1[(tl * 16 + i) * NN + n2]);
                    float2 v2 = __ldcg((const float2*)&g_G2[(tl * 16 + i) * NN + n2]);
                    float h0 = Hs[(i * 3 + a) * 3 + 0];
                    float h1 = Hs[(i * 3 + a) * 3 + 1];
                    float h2 = Hs[(i * 3 + a) * 3 + 2];
                    acc.x += h0 * v0.x + h1 * v1.x + h2 * v2.x;
                    acc.y += h0 * v0.y + h1 * v1.y + h2 * v2.y;
                }
            }
            out[(n2    ) * TT + tau] = acc.x;
            out[(n2 + 1) * TT + tau] = acc.y;
        }
    }
}

// ---------------- launch ---------------------------------------------------------
extern "C" void kernel_launch(void* const* d_in, const int* in_sizes, int n_in,
                              void* d_out, int out_size)
{
    const float* X    = (const float*)d_in[0];
    const float* Sg   = (const float*)d_in[1];
    const float* s    = (const float*)d_in[2];
    const float* h_e1 = (const float*)d_in[3];
    const float* h_e2 = (const float*)d_in[4];
    const float* h_d1 = (const float*)d_in[5];
    const float* h_d2 = (const float*)d_in[6];
    float* out = (float*)d_out;

    mega<<<NB, 128>>>(X, Sg, s, h_e1, h_e2, h_d1, h_d2, out);
}

// round 8
// speedup vs baseline: 1.7167x; 1.1501x over previous
#include <cuda_runtime.h>
#include <cstdint>

// GTConvAE — fused persistent kernel, R8.
// Kronecker identity: S^k x[tau] = sum_{a,b<3} c_k[a][b] * Sg^b x[(tau-a) mod t].
// Layer = two GEMMs (G1=Sg@act, G2=Sg2@act) + 9-term combine with folded filters.
// Encoder fuses maxpool+relu; decoder exploits zero-stuffed upsampling.
// R8: 128 blocks x 128 threads (1 block/SM, uniform stages), 24mx16j tiles with
// 2 j-tiles per block, A band resident in smem across all three big GEMM stages,
// double-buffered B, 3x1 micro-tile.

#define NN  192
#define TT  32
#define NB  128
#define KS  196   // smem row stride in floats

// ---------------- scratch --------------------------------------------------------
__device__ float g_Sg2 [NN * NN];
__device__ float g_G1  [256 * NN];   // act-layout [j][n]; also P = Sg@X for e1
__device__ float g_G2  [256 * NN];
__device__ float g_actA[256 * NN];
__device__ float g_actB[256 * NN];
__device__ unsigned g_cnt = 0;
__device__ unsigned g_gen = 0;

// ---------------- grid barrier: release-arrive / acquire-poll --------------------
__device__ __forceinline__ void grid_barrier()
{
    __syncthreads();
    if (threadIdx.x == 0) {
        unsigned gen;
        asm volatile("ld.relaxed.gpu.u32 %0, [%1];"
                     : "=r"(gen) : "l"(&g_gen) : "memory");
        unsigned prev;
        asm volatile("atom.release.gpu.add.u32 %0, [%1], %2;"
                     : "=r"(prev) : "l"(&g_cnt), "r"(1u) : "memory");
        if (prev == NB - 1) {
            asm volatile("st.relaxed.gpu.u32 [%0], %1;"
                         :: "l"(&g_cnt), "r"(0u) : "memory");
            asm volatile("st.release.gpu.u32 [%0], %1;"
                         :: "l"(&g_gen), "r"(gen + 1u) : "memory");
        } else {
            unsigned cur;
            do {
                __nanosleep(16);
                asm volatile("ld.acquire.gpu.u32 %0, [%1];"
                             : "=r"(cur) : "l"(&g_gen) : "memory");
            } while (cur == gen);
        }
    }
    __syncthreads();
}

// ---------------- cp.async helpers ----------------------------------------------
__device__ __forceinline__ void cp16(float* dst, const float* src, bool cg)
{
    uint32_t d = (uint32_t)__cvta_generic_to_shared(dst);
    if (cg)
        asm volatile("cp.async.cg.shared.global [%0], [%1], 16;" :: "r"(d), "l"(src));
    else
        asm volatile("cp.async.ca.shared.global [%0], [%1], 16;" :: "r"(d), "l"(src));
}
__device__ __forceinline__ void cp_wait_all()
{
    asm volatile("cp.async.wait_all;" ::: "memory");
}

// ---------------- tile loaders ---------------------------------------------------
// A band: 24 rows x 192 k -> As[m][k]
__device__ __forceinline__ void loadA24(const float* __restrict__ A, int m0,
                                        bool cg, float* As)
{
    #pragma unroll
    for (int r = 0; r < 9; r++) {
        int op = threadIdx.x + 128 * r;          // 0..1151
        int ml = op / 48, kq = op - ml * 48;
        cp16(&As[ml * KS + 4 * kq], &A[(m0 + ml) * NN + 4 * kq], cg);
    }
}
// B tile (act layout [j*NN+k]): 16 rows x 192 k -> Bs[j][k]
__device__ __forceinline__ void loadB16(const float* __restrict__ Bg, int j0,
                                        float* Bsb)
{
    #pragma unroll
    for (int r = 0; r < 6; r++) {
        int op = threadIdx.x + 128 * r;          // 0..767
        int jl = op / 48, kq = op - jl * 48;
        cp16(&Bsb[jl * KS + 4 * kq], &Bg[(j0 + jl) * NN + 4 * kq], true);
    }
}

// ---------------- compute one 24m x 16j tile -------------------------------------
template <bool CROW>
__device__ __forceinline__ void tile_compute(const float* __restrict__ As,
                                             const float* __restrict__ Bsb,
                                             float* __restrict__ C, int m0, int j0)
{
    const int tid = threadIdx.x;
    const int tx = tid & 15, ty = tid >> 4;      // j col, m base (0..7)
    float acc0 = 0.f, acc1 = 0.f, acc2 = 0.f;
    const float* bp  = Bsb + tx * KS;
    const float* ap0 = As + ty * KS;
    const float* ap1 = ap0 + 8 * KS;
    const float* ap2 = ap0 + 16 * KS;
    #pragma unroll 8
    for (int k = 0; k < NN; k += 4) {
        float4 b  = *(const float4*)(bp + k);
        float4 a0 = *(const float4*)(ap0 + k);
        float4 a1 = *(const float4*)(ap1 + k);
        float4 a2 = *(const float4*)(ap2 + k);
        acc0 += a0.x * b.x; acc0 += a0.y * b.y; acc0 += a0.z * b.z; acc0 += a0.w * b.w;
        acc1 += a1.x * b.x; acc1 += a1.y * b.y; acc1 += a1.z * b.z; acc1 += a1.w * b.w;
        acc2 += a2.x * b.x; acc2 += a2.y * b.y; acc2 += a2.z * b.z; acc2 += a2.w * b.w;
    }
    const int j = j0 + tx;
    if (CROW) {
        C[(m0 + ty     ) * NN + j] = acc0;
        C[(m0 + ty +  8) * NN + j] = acc1;
        C[(m0 + ty + 16) * NN + j] = acc2;
    } else {
        C[j * NN + m0 + ty     ] = acc0;
        C[j * NN + m0 + ty +  8] = acc1;
        C[j * NN + m0 + ty + 16] = acc2;
    }
}

// ---------------- big GEMM stage: 2 j-tiles, double-buffered B -------------------
template <bool LOADA>
__device__ void big_stage(const float* __restrict__ A, bool acg,
                          const float* __restrict__ Bact,
                          float* __restrict__ C, int m0, int j0,
                          float* As, float* Bs0, float* Bs1)
{
    if (LOADA) loadA24(A, m0, acg, As);
    loadB16(Bact, j0, Bs0);
    cp_wait_all(); __syncthreads();
    loadB16(Bact, j0 + 16, Bs1);
    tile_compute<false>(As, Bs0, C, m0, j0);
    cp_wait_all(); __syncthreads();
    tile_compute<false>(As, Bs1, C, m0, j0 + 16);
}

// ---------------- S0 tile: B from column-slices (Sg or X) ------------------------
template <int BMODE, bool CROW>   // BMODE 1: Sg [k*NN+j], 2: X [k*TT+j]
__device__ void s0_tile(const float* __restrict__ A, const float* __restrict__ Bg,
                        int j0, float* __restrict__ C, int m0,
                        float* As, float* Bs0)
{
    loadA24(A, m0, false, As);
    const int tid = threadIdx.x;
    #pragma unroll
    for (int r = 0; r < 24; r++) {
        int idx = tid + 128 * r;                 // 0..3071
        int jl = idx & 15, kk = idx >> 4;
        Bs0[jl * KS + kk] = (BMODE == 1) ? Bg[kk * NN + j0 + jl]
                                         : Bg[kk * TT + j0 + jl];
    }
    cp_wait_all(); __syncthreads();
    tile_compute<CROW>(As, Bs0, C, m0, j0);
}

// ---------------- folded filters -------------------------------------------------
__device__ __forceinline__ float fold_H(const float* __restrict__ h3,
                                        const float sv[4], int a, int b)
{
    float c0 = (a == 0 && b == 0) ? 1.f : 0.f;
    float c1 = (a < 2 && b < 2) ? sv[a * 2 + b] : 0.f;
    float c2 = 0.f;
    #pragma unroll
    for (int a1 = 0; a1 < 2; a1++)
        #pragma unroll
        for (int b1 = 0; b1 < 2; b1++) {
            int a2 = a - a1, b2 = b - b1;
            if (a2 >= 0 && a2 < 2 && b2 >= 0 && b2 < 2)
                c2 += sv[a1 * 2 + b1] * sv[a2 * 2 + b2];
        }
    return h3[0] * c0 + h3[1] * c1 + h3[2] * c2;
}

__device__ __forceinline__ void build_Hs(float* Hs, const float* __restrict__ h,
                                         const float sv[4], int CI, int OT, int ob)
{
    for (int idx = threadIdx.x; idx < CI * 9 * OT; idx += 128) {
        int oo = idx % OT;
        int tmp = idx / OT;
        int b = tmp % 3, a = (tmp / 3) % 3, i = tmp / 9;
        Hs[idx] = fold_H(&h[((ob + oo) * CI + i) * 3], sv, a, b);
    }
}

// ---------------- encoder combine (e2): n-pair threads, float2 loads -------------
template <int CI, int CO, int OT>
__device__ void combine_enc2(const float* __restrict__ G0,
                             const float* __restrict__ G1,
                             const float* __restrict__ G2,
                             const float* __restrict__ h, const float* __restrict__ sp,
                             float* __restrict__ out, int t, int tp, int ob, float* Hs)
{
    const int tid = threadIdx.x;
    const float sv[4] = { sp[0], sp[1], sp[2], sp[3] };
    build_Hs(Hs, h, sv, CI, OT, ob);
    __syncthreads();
    if (tid < 96) {
        const int n2 = 2 * tid;
        float2 acc0[OT], acc1[OT];
        #pragma unroll
        for (int o = 0; o < OT; o++) {
            acc0[o] = make_float2(0.f, 0.f); acc1[o] = make_float2(0.f, 0.f);
        }
        #pragma unroll
        for (int tt = 0; tt < 4; tt++) {
            int src = (2 * tp - 2 + tt + t) & (t - 1);
            #pragma unroll
            for (int i = 0; i < CI; i++) {
                float2 v0 = __ldcg((const float2*)&G0[(src * CI + i) * NN + n2]);
                float2 v1 = __ldcg((const float2*)&G1[(src * CI + i) * NN + n2]);
                float2 v2 = __ldcg((const float2*)&G2[(src * CI + i) * NN + n2]);
                if (tt <= 2) {
                    const float* Hp = &Hs[(i * 3 + (2 - tt)) * 3 * OT];
                    #pragma unroll
                    for (int o = 0; o < OT; o++) {
                        float h0 = Hp[o], h1 = Hp[OT + o], h2 = Hp[2 * OT + o];
                        acc0[o].x += h0 * v0.x + h1 * v1.x + h2 * v2.x;
                        acc0[o].y += h0 * v0.y + h1 * v1.y + h2 * v2.y;
                    }
                }
                if (tt >= 1) {
                    const float* Hp = &Hs[(i * 3 + (3 - tt)) * 3 * OT];
                    #pragma unroll
                    for (int o = 0; o < OT; o++) {
                        float h0 = Hp[o], h1 = Hp[OT + o], h2 = Hp[2 * OT + o];
                        acc1[o].x += h0 * v0.x + h1 * v1.x + h2 * v2.x;
                        acc1[o].y += h0 * v0.y + h1 * v1.y + h2 * v2.y;
                    }
                }
            }
        }
        #pragma unroll
        for (int o = 0; o < OT; o++) {
            float2 r;
            r.x = fmaxf(fmaxf(acc0[o].x, acc1[o].x), 0.f);
            r.y = fmaxf(fmaxf(acc0[o].y, acc1[o].y), 0.f);
            *(float2*)&out[(tp * CO + ob + o) * NN + n2] = r;
        }
    }
}

// ---------------- decoder combine: zero-stuffed input, n-pair threads ------------
template <int CI, int CO, int OT>
__device__ void combine_dec2(const float* __restrict__ G0,
                             const float* __restrict__ G1,
                             const float* __restrict__ G2,
                             const float* __restrict__ h, const float* __restrict__ sp,
                             float* __restrict__ out, int t, int tau, int ob, float* Hs)
{
    const int tid = threadIdx.x;
    const float sv[4] = { sp[0], sp[1], sp[2], sp[3] };
    build_Hs(Hs, h, sv, CI, OT, ob);
    __syncthreads();
    if (tid < 96) {
        const int n2 = 2 * tid;
        float2 acc[OT];
        #pragma unroll
        for (int o = 0; o < OT; o++) acc[o] = make_float2(0.f, 0.f);
        #pragma unroll
        for (int a = 0; a < 3; a++) {
            int src = tau - a; if (src < 0) src += t;
            if (src & 1) continue;             // zero-stuffed upsample
            int tl = src >> 1;
            #pragma unroll 16
            for (int i = 0; i < CI; i++) {
                float2 v0 = __ldcg((const float2*)&G0[(tl * CI + i) * NN + n2]);
                float2 v1 = __ldcg((const float2*)&G1[(tl * CI + i) * NN + n2]);
                float2 v2 = __ldcg((const float2*)&G2[(tl * CI + i) * NN + n2]);
                const float* Hp = &Hs[(i * 3 + a) * 3 * OT];
                #pragma unroll
                for (int o = 0; o < OT; o++) {
                    float h0 = Hp[o], h1 = Hp[OT + o], h2 = Hp[2 * OT + o];
                    acc[o].x += h0 * v0.x + h1 * v1.x + h2 * v2.x;
                    acc[o].y += h0 * v0.y + h1 * v1.y + h2 * v2.y;
                }
            }
        }
        #pragma unroll
        for (int o = 0; o < OT; o++) {
            float2 r;
            r.x = fmaxf(acc[o].x, 0.f);
            r.y = fmaxf(acc[o].y, 0.f);
            *(float2*)&out[(tau * CO + ob + o) * NN + n2] = r;
        }
    }
}

// ---------------- persistent mega-kernel ----------------------------------------
__global__ __launch_bounds__(128, 1) void mega(
    const float* __restrict__ X,    const float* __restrict__ Sg,
    const float* __restrict__ s,    const float* __restrict__ h_e1,
    const float* __restrict__ h_e2, const float* __restrict__ h_d1,
    const float* __restrict__ h_d2, float* __restrict__ out)
{
    __shared__ float As[24 * KS];    // 18.8 KB — persistent A band for S3/S5/S7
    __shared__ float Bs0[16 * KS];   // 12.5 KB
    __shared__ float Bs1[16 * KS];   // 12.5 KB
    __shared__ float Hs[576];        //  2.3 KB
    __shared__ float G2s[96];        //  e1 mini-GEMM result (4 src x 24 n)

    const int bid = blockIdx.x;
    const int tid = threadIdx.x;

    // big-GEMM identity (fixed across S3/S5/S7)
    const int mat = bid >> 6;                 // 0: Sg, 1: Sg2
    const int sub = bid & 63;
    const int gm0 = (sub >> 3) * 24;          // 8 m-bands of 24
    const int gj0 = (sub & 7) * 32;           // 8 j-pairs (2 x 16)

    // ======== S0: Sg2 (96 tiles) + P = Sg@X (16 tiles) ========
    if (bid < 96) {
        int mb = bid / 12, jt = bid % 12;
        s0_tile<1, true>(Sg, Sg, jt * 16, g_Sg2, mb * 24, As, Bs0);
    } else if (bid < 112) {
        int b2 = bid - 96;
        int mb = b2 >> 1, jt = b2 & 1;
        s0_tile<2, false>(Sg, X, jt * 16, g_G1, mb * 24, As, Bs0);
    }
    grid_barrier();

    // ======== S1': e1 combine with fused mini-GEMM for G2 ========
    // 128 blocks = 16 tp x 8 n-bands of 24.
    {
        const int tp = bid & 15, nb = bid >> 4;
        const int n0 = nb * 24;
        loadA24(Sg, n0, false, As);           // Sg rows n0..n0+23
        #pragma unroll
        for (int r = 0; r < 2; r++) {         // P rows for 4 source taus
            int op = tid + 128 * r;
            if (op < 192) {
                int ttl = op / 48, kq = op - ttl * 48;
                int src = (2 * tp - 2 + ttl + TT) & (TT - 1);
                cp16(&Bs0[ttl * KS + 4 * kq], &g_G1[src * NN + 4 * kq], true);
            }
        }
        const float sv[4] = { s[0], s[1], s[2], s[3] };
        for (int idx = tid; idx < 144; idx += 128) {   // CI=1, OT=16
            int o = idx & 15, ab = idx >> 4;
            Hs[idx] = fold_H(&h_e1[o * 3], sv, ab / 3, ab % 3);
        }
        cp_wait_all(); __syncthreads();
        if (tid < 96) {                       // mini-GEMM: 24 n x 4 src
            int nl = tid % 24, st = tid / 24;
            float acc = 0.f;
            const float* ap = As + nl * KS;
            const float* bp = Bs0 + st * KS;
            #pragma unroll 12
            for (int k = 0; k < NN; k += 4) {
                float4 a = *(const float4*)(ap + k);
                float4 b = *(const float4*)(bp + k);
                acc += a.x * b.x; acc += a.y * b.y; acc += a.z * b.z; acc += a.w * b.w;
            }
            G2s[st * 24 + nl] = acc;
        }
        __syncthreads();
        if (tid < 96) {                       // combine: 24 n x 4 o-groups of 4
            int nl = tid % 24, og = tid / 24;
            int n = n0 + nl;
            float acc0[4] = {0.f, 0.f, 0.f, 0.f};
            float acc1[4] = {0.f, 0.f, 0.f, 0.f};
            #pragma unroll
            for (int ttl = 0; ttl < 4; ttl++) {
                int src = (2 * tp - 2 + ttl + TT) & (TT - 1);
                float v0 = X[n * TT + src];
                float v1 = Bs0[ttl * KS + n];       // P[src][n]
                float v2 = G2s[ttl * 24 + nl];
                if (ttl <= 2) {
                    int a = 2 - ttl;
                    #pragma unroll
                    for (int oo = 0; oo < 4; oo++) {
                        int o = og * 4 + oo;
                        acc0[oo] += Hs[(a * 3 + 0) * 16 + o] * v0
                                  + Hs[(a * 3 + 1) * 16 + o] * v1
                                  + Hs[(a * 3 + 2) * 16 + o] * v2;
                    }
                }
                if (ttl >= 1) {
                    int a = 3 - ttl;
                    #pragma unroll
                    for (int oo = 0; oo < 4; oo++) {
                        int o = og * 4 + oo;
                        acc1[oo] += Hs[(a * 3 + 0) * 16 + o] * v0
                                  + Hs[(a * 3 + 1) * 16 + o] * v1
                                  + Hs[(a * 3 + 2) * 16 + o] * v2;
                    }
                }
            }
            #pragma unroll
            for (int oo = 0; oo < 4; oo++) {
                int o = og * 4 + oo;
                g_actA[(tp * 16 + o) * NN + n] = fmaxf(fmaxf(acc0[oo], acc1[oo]), 0.f);
            }
        }
    }
    grid_barrier();

    // ======== S3: e2 GEMMs (loads persistent A band) ========
    if (mat == 0)
        big_stage<true>(Sg, false, g_actA, g_G1, gm0, gj0, As, Bs0, Bs1);
    else
        big_stage<true>(g_Sg2, true, g_actA, g_G2, gm0, gj0, As, Bs0, Bs1);
    grid_barrier();

    // ======== S4: combine e2 -> actB ========
    {
        int tp = bid & 7, obg = bid >> 3;      // 16 groups of OT=2
        combine_enc2<16, 32, 2>(g_actA, g_G1, g_G2, h_e2, s,
                                g_actB, 16, tp, obg * 2, Hs);
    }
    grid_barrier();

    // ======== S5: d1 GEMMs (A resident) ========
    big_stage<false>(nullptr, false, g_actB, mat ? g_G2 : g_G1, gm0, gj0, As, Bs0, Bs1);
    grid_barrier();

    // ======== S6: combine d1 -> actA ========
    {
        int tau = bid & 15, obg = bid >> 4;    // 8 groups of OT=2
        combine_dec2<32, 16, 2>(g_actB, g_G1, g_G2, h_d1, s,
                                g_actA, 16, tau, obg * 2, Hs);
    }
    grid_barrier();

    // ======== S7: d2 GEMMs (A resident) ========
    big_stage<false>(nullptr, false, g_actA, mat ? g_G2 : g_G1, gm0, gj0, As, Bs0, Bs1);
    grid_barrier();

    // ======== S8: final combine d2 -> out (N, T) ========
    if (bid < 32) {
        const int tau = bid;
        const float sv[4] = { s[0], s[1], s[2], s[3] };
        for (int idx = tid; idx < 144; idx += 128) {   // CI=16, OT=1
            int b = idx % 3, a = (idx / 3) % 3, i = idx / 9;
            Hs[idx] = fold_H(&h_d2[i * 3], sv, a, b);
        }
        __syncthreads();
        if (tid < 96) {
            const int n2 = 2 * tid;
            float2 acc = make_float2(0.f, 0.f);
            #pragma unroll
            for (int a = 0; a < 3; a++) {
                int src = tau - a; if (src < 0) src += TT;
                if (src & 1) continue;
                int tl = src >> 1;
                #pragma unroll
                for (int i = 0; i < 16; i++) {
                    float2 v0 = __ldcg((const float2*)&g_actA[(tl * 16 + i) * NN + n2]);
                    float2 v1 = __ldcg((const float2*)&g_G1[(tl * 16 + i) * NN + n2]);
                    float2 v2 = __ldcg((const float2*)&g_G2[(tl * 16 + i) * NN + n2]);
                    float h0 = Hs[(i * 3 + a) * 3 + 0];
                    float h1 = Hs[(i * 3 + a) * 3 + 1];
                    float h2 = Hs[(i * 3 + a) * 3 + 2];
                    acc.x += h0 * v0.x + h1 * v1.x + h2 * v2.x;
                    acc.y += h0 * v0.y + h1 * v1.y + h2 * v2.y;
                }
            }
            out[(n2    ) * TT + tau] = acc.x;
            out[(n2 + 1) * TT + tau] = acc.y;
        }
    }
}

// ---------------- launch ---------------------------------------------------------
extern "C" void kernel_launch(void* const* d_in, const int* in_sizes, int n_in,
                              void* d_out, int out_size)
{
    const float* X    = (const float*)d_in[0];
    const float* Sg   = (const float*)d_in[1];
    const float* s    = (const float*)d_in[2];
    const float* h_e1 = (const float*)d_in[3];
    const float* h_e2 = (const float*)d_in[4];
    const float* h_d1 = (const float*)d_in[5];
    const float* h_d2 = (const float*)d_in[6];
    float* out = (float*)d_out;

    mega<<<NB, 128>>>(X, Sg, s, h_e1, h_e2, h_d1, h_d2, out);
}